// round 11
// baseline (speedup 1.0000x reference)
#include <cuda_runtime.h>
#include <cuda_bf16.h>
#include <cstdint>

#define B 1024
#define T 128
#define INP 5
#define H 100
#define G4 400
#define MTOT (B*T)
#define KPAD 208

// ---------------- scratch (device globals; no runtime allocation) ----------
__device__ float g_h0s[B * 2 * H];            // [b][200] h0 at t=T-1
__device__ float g_xg1[(size_t)MTOT * G4];    // [t*B+b][n'] layer1-fwd gates (+bias), gate-interleaved
__device__ float g_h1f[B * H];
__device__ __nv_bfloat16 g_Ah[(size_t)MTOT * KPAD];   // h0 hi, [t*B+b][k]; cols 200..207 = 0
__device__ __nv_bfloat16 g_Al[(size_t)MTOT * KPAD];
__device__ __nv_bfloat16 g_Bh[400 * KPAD];            // W_ih_l1f rows gate-interleaved
__device__ __nv_bfloat16 g_Bl[400 * KPAD];

typedef unsigned long long u64;

__device__ __forceinline__ u64 pk2(float a, float b) {
    u64 r; asm("mov.b64 %0, {%1,%2};" : "=l"(r) : "f"(a), "f"(b)); return r;
}
__device__ __forceinline__ void upk2(u64 v, float& a, float& b) {
    asm("mov.b64 {%0,%1}, %2;" : "=f"(a), "=f"(b) : "l"(v));
}
__device__ __forceinline__ u64 ffma2(u64 a, u64 b, u64 c) {
    asm("fma.rn.f32x2 %0, %1, %2, %0;" : "+l"(c) : "l"(a), "l"(b)); return c;
}
__device__ __forceinline__ float fsig(float x) {
    float e; asm("ex2.approx.f32 %0, %1;" : "=f"(e) : "f"(x * -1.4426950408889634f));
    float r; asm("rcp.approx.f32 %0, %1;" : "=f"(r) : "f"(e + 1.0f));
    return r;
}
__device__ __forceinline__ float ftanh_(float x) {
    float e; asm("ex2.approx.f32 %0, %1;" : "=f"(e) : "f"(x * -2.885390081777927f));
    float r; asm("rcp.approx.f32 %0, %1;" : "=f"(r) : "f"(e + 1.0f));
    return fmaf(2.0f, r, -1.0f);
}
__device__ __forceinline__ uint32_t smem_u32(const void* p) {
    uint32_t a;
    asm("{ .reg .u64 t; cvta.to.shared.u64 t, %1; cvt.u32.u64 %0, t; }" : "=r"(a) : "l"(p));
    return a;
}

#define MMA_BF16(ac, a0,a1,a2,a3, b0,b1) \
    asm volatile("mma.sync.aligned.m16n8k16.row.col.f32.bf16.bf16.f32 " \
        "{%0,%1,%2,%3}, {%4,%5,%6,%7}, {%8,%9}, {%0,%1,%2,%3};" \
        : "+f"((ac)[0]), "+f"((ac)[1]), "+f"((ac)[2]), "+f"((ac)[3]) \
        : "r"(a0), "r"(a1), "r"(a2), "r"(a3), "r"(b0), "r"(b1))

// ============================================================================
// TENSOR-CORE RECURRENCE, 2 INDEPENDENT GROUPS per CTA (anti-phase overlap).
// CTA = 32 batches, 512 thr / 16 warps. Group = 8 warps x 16 batches, its own
// named barrier; W smem (hi/lo bf16, gate-interleaved n'=j*4+gate) shared.
// Per group step: MMA (7 kc x 7 slots x 3 split products, x-proj folded in
// k=100..104) -> shfl gate exchange -> in-register activations -> h into
// double-buffered per-group A staging -> named bar -> (mode0) coalesced
// smem->global copy of h hi/lo.
// mode 0: layer0 (grid 64: dir=bid>>5, 32 batches), emits g_Ah/g_Al + g_h0s.
// mode 1: layer1 fwd (grid 32), acc init from g_xg1, emits g_h1f.
// SMEM: Wh[400][120] | Wl | per-group A bufs x2 (Ah[16][120] + Al)
// ============================================================================
#define KSB     240
#define OFF_WL  96000
#define OFF_A   192000
#define ABUF    7680
#define GSTRIDE 15360
#define RC_SMEM 222720
#define NTHR    512

__global__ void __launch_bounds__(NTHR, 1) lstm_rec_mma(
    const float* __restrict__ xg,
    const float* __restrict__ x,
    const float* __restrict__ whf, const float* __restrict__ whb,
    const float* __restrict__ wihf, const float* __restrict__ wihb,
    const float* __restrict__ bihf, const float* __restrict__ bhhf,
    const float* __restrict__ bihb, const float* __restrict__ bhhb,
    int mode)
{
    extern __shared__ char smc[];
    const uint32_t sb = smem_u32(smc);
    const int tid = threadIdx.x, wid = tid >> 5, lane = tid & 31;
    const int grp = wid >> 3, wper = wid & 7, gtid = tid & 255;
    const int g = lane >> 2, t4 = lane & 3;
    int dir, b0;
    if (mode == 0) { dir = blockIdx.x >> 5; b0 = (blockIdx.x & 31) * 32; }
    else           { dir = 0;               b0 = blockIdx.x * 32; }
    const int bg0 = b0 + grp * 16;
    const float* wp  = dir ? whb  : whf;
    const float* wip = dir ? wihb : wihf;
    const float* bi_ = dir ? bihb : bihf;
    const float* bh_ = dir ? bhhb : bhhf;

    // zero W pads + A staging (h=0 initial state)
    for (int i = tid; i < (RC_SMEM >> 4); i += NTHR)
        ((uint4*)smc)[i] = make_uint4(0, 0, 0, 0);
    __syncthreads();
    // W fill: row n' = j*4+gate <- orig row gate*100+j ; k 0..99 = Whh
    for (int i = tid; i < 400 * 100; i += NTHR) {
        int r = i / 100, k = i - r * 100;
        int np = (r % 100) * 4 + r / 100;
        float w = wp[i];
        __nv_bfloat16 hb = __float2bfloat16(w);
        __nv_bfloat16 lb = __float2bfloat16(w - __bfloat162float(hb));
        *(__nv_bfloat16*)(smc + np * KSB + k * 2) = hb;
        *(__nv_bfloat16*)(smc + OFF_WL + np * KSB + k * 2) = lb;
    }
    if (mode == 0) {
        for (int i = tid; i < 400 * INP; i += NTHR) {
            int r = i / INP, d = i - r * INP;
            int np = (r % 100) * 4 + r / 100;
            float w = wip[i];
            __nv_bfloat16 hb = __float2bfloat16(w);
            __nv_bfloat16 lb = __float2bfloat16(w - __bfloat162float(hb));
            *(__nv_bfloat16*)(smc + np * KSB + (100 + d) * 2) = hb;
            *(__nv_bfloat16*)(smc + OFF_WL + np * KSB + (100 + d) * 2) = lb;
        }
        if (gtid < 16 * INP) {   // first-step x into this group's buf0
            int bb = gtid / INP, d = gtid - (gtid / INP) * INP;
            int tg0 = dir ? (T - 1) : 0;
            float xv = x[((size_t)(bg0 + bb) * T + tg0) * INP + d];
            __nv_bfloat16 hb = __float2bfloat16(xv);
            __nv_bfloat16 lb = __float2bfloat16(xv - __bfloat162float(hb));
            *(__nv_bfloat16*)(smc + OFF_A + grp * GSTRIDE + bb * KSB + (100 + d) * 2) = hb;
            *(__nv_bfloat16*)(smc + OFF_A + grp * GSTRIDE + 3840 + bb * KSB + (100 + d) * 2) = lb;
        }
    }

    // 7 slots/warp within group: tile = wper + 8*i (valid < 50; dummies -> 0)
    int  tl[7]; bool tv[7];
    float br[7][2];
    #pragma unroll
    for (int i = 0; i < 7; i++) {
        int t = wper + 8 * i;
        tv[i] = (t < 50); tl[i] = tv[i] ? t : 0;
        br[i][0] = br[i][1] = 0.f;
        if (mode == 0 && tv[i]) {
            int np = t * 8 + 2 * t4;
            int r0 = (np & 3) * 100 + (np >> 2);
            int r1 = ((np + 1) & 3) * 100 + ((np + 1) >> 2);
            br[i][0] = bi_[r0] + bh_[r0];
            br[i][1] = bi_[r1] + bh_[r1];
        }
    }
    float cst[7];
    #pragma unroll
    for (int i = 0; i < 7; i++) cst[i] = 0.f;

    float xp[7][4];
    if (mode == 1) {
        #pragma unroll
        for (int i = 0; i < 7; i++) {
            xp[i][0] = xp[i][1] = xp[i][2] = xp[i][3] = 0.f;
            if (tv[i]) {
                const float* p0 = xg + (size_t)(bg0 + g) * 400 + tl[i] * 8 + 2 * t4;
                float2 v0 = *(const float2*)p0;
                float2 v1 = *(const float2*)(p0 + 3200);
                xp[i][0] = v0.x; xp[i][1] = v0.y; xp[i][2] = v1.x; xp[i][3] = v1.y;
            }
        }
    }
    __syncthreads();

    const uint32_t aGrp = sb + OFF_A + grp * GSTRIDE;
    const int barid = grp + 1;

    for (int ts = 0; ts < T; ts++) {
        const int cur = ts & 1, nxt = cur ^ 1;
        const int tg = dir ? (T - 1 - ts) : ts;

        float acc[7][4];
        if (mode == 0) {
            #pragma unroll
            for (int i = 0; i < 7; i++) {
                acc[i][0] = br[i][0]; acc[i][1] = br[i][1];
                acc[i][2] = br[i][0]; acc[i][3] = br[i][1];
            }
        } else {
            #pragma unroll
            for (int i = 0; i < 7; i++) {
                acc[i][0] = xp[i][0]; acc[i][1] = xp[i][1];
                acc[i][2] = xp[i][2]; acc[i][3] = xp[i][3];
            }
            if (ts + 1 < T) {
                #pragma unroll
                for (int i = 0; i < 7; i++) {
                    if (tv[i]) {
                        const float* p0 = xg + ((size_t)(ts + 1) * B + bg0 + g) * 400 + tl[i] * 8 + 2 * t4;
                        float2 v0 = *(const float2*)p0;
                        float2 v1 = *(const float2*)(p0 + 3200);
                        xp[i][0] = v0.x; xp[i][1] = v0.y; xp[i][2] = v1.x; xp[i][3] = v1.y;
                    }
                }
            }
        }
        float xv = 0.f;
        if (mode == 0 && gtid < 16 * INP && ts + 1 < T) {
            int bb = gtid / INP, d = gtid - (gtid / INP) * INP;
            int tgn = dir ? (tg - 1) : (tg + 1);
            xv = x[((size_t)(bg0 + bb) * T + tgn) * INP + d];
        }

        // ---- MMA: 7 kc x 7 slots x 3 split products (product-outer) ----
        const uint32_t aBase = aGrp + cur * ABUF;
        #pragma unroll
        for (int kc = 0; kc < 7; kc++) {
            uint32_t ah[4], al[4];
            uint32_t aa = aBase + (lane & 15) * KSB + (lane >> 4) * 16 + kc * 32;
            asm volatile("ldmatrix.sync.aligned.m8n8.x4.shared.b16 {%0,%1,%2,%3}, [%4];"
                : "=r"(ah[0]), "=r"(ah[1]), "=r"(ah[2]), "=r"(ah[3]) : "r"(aa));
            asm volatile("ldmatrix.sync.aligned.m8n8.x4.shared.b16 {%0,%1,%2,%3}, [%4];"
                : "=r"(al[0]), "=r"(al[1]), "=r"(al[2]), "=r"(al[3]) : "r"(aa + 3840));

            uint32_t wh[7][2], wl[7][2];
            #pragma unroll
            for (int p = 0; p < 3; p++) {   // paired x4 loads for slots 2p, 2p+1
                int m = lane >> 3;
                int tt = tl[2 * p + (m >> 1)];
                uint32_t wa = sb + (8 * tt + (lane & 7)) * KSB + (m & 1) * 16 + kc * 32;
                asm volatile("ldmatrix.sync.aligned.m8n8.x4.shared.b16 {%0,%1,%2,%3}, [%4];"
                    : "=r"(wh[2*p][0]), "=r"(wh[2*p][1]), "=r"(wh[2*p+1][0]), "=r"(wh[2*p+1][1])
                    : "r"(wa));
                asm volatile("ldmatrix.sync.aligned.m8n8.x4.shared.b16 {%0,%1,%2,%3}, [%4];"
                    : "=r"(wl[2*p][0]), "=r"(wl[2*p][1]), "=r"(wl[2*p+1][0]), "=r"(wl[2*p+1][1])
                    : "r"(wa + OFF_WL));
            }
            {
                uint32_t wa = sb + (8 * tl[6] + (lane & 7)) * KSB + ((lane >> 3) & 1) * 16 + kc * 32;
                asm volatile("ldmatrix.sync.aligned.m8n8.x2.shared.b16 {%0,%1}, [%2];"
                    : "=r"(wh[6][0]), "=r"(wh[6][1]) : "r"(wa));
                asm volatile("ldmatrix.sync.aligned.m8n8.x2.shared.b16 {%0,%1}, [%2];"
                    : "=r"(wl[6][0]), "=r"(wl[6][1]) : "r"(wa + OFF_WL));
            }
            #pragma unroll
            for (int i = 0; i < 7; i++)
                MMA_BF16(acc[i], ah[0], ah[1], ah[2], ah[3], wh[i][0], wh[i][1]);
            #pragma unroll
            for (int i = 0; i < 7; i++)
                MMA_BF16(acc[i], al[0], al[1], al[2], al[3], wh[i][0], wh[i][1]);
            #pragma unroll
            for (int i = 0; i < 7; i++)
                MMA_BF16(acc[i], ah[0], ah[1], ah[2], ah[3], wl[i][0], wl[i][1]);
        }

        // ---- gate exchange + in-register activations ----
        #pragma unroll
        for (int i = 0; i < 7; i++) {
            if (tv[i]) {
                float s0 = __shfl_xor_sync(0xffffffffu, acc[i][0], 1);
                float s1 = __shfl_xor_sync(0xffffffffu, acc[i][1], 1);
                float s2 = __shfl_xor_sync(0xffffffffu, acc[i][2], 1);
                float s3 = __shfl_xor_sync(0xffffffffu, acc[i][3], 1);
                bool odd = (t4 & 1);
                float gi = odd ? s2 : acc[i][0];
                float gf = odd ? s3 : acc[i][1];
                float gg = odd ? acc[i][2] : s0;
                float go = odd ? acc[i][3] : s1;
                float cv = fsig(gf) * cst[i] + fsig(gi) * ftanh_(gg);
                cst[i] = cv;
                float h = fsig(go) * ftanh_(cv);
                __nv_bfloat16 hh = __float2bfloat16(h);
                __nv_bfloat16 hl = __float2bfloat16(h - __bfloat162float(hh));
                int bu = g + (odd ? 8 : 0);
                int ju = 2 * tl[i] + (t4 >> 1);
                uint32_t off = OFF_A + grp * GSTRIDE + nxt * ABUF + bu * KSB + ju * 2;
                *(__nv_bfloat16*)(smc + off) = hh;
                *(__nv_bfloat16*)(smc + off + 3840) = hl;
                if (mode == 0) {
                    if (tg == T - 1)
                        g_h0s[(size_t)(bg0 + bu) * 200 + dir * 100 + ju] = h;
                } else if (ts == T - 1) {
                    g_h1f[(size_t)(bg0 + bu) * 100 + ju] = h;
                }
            }
        }
        if (mode == 0 && gtid < 16 * INP && ts + 1 < T) {
            int bb = gtid / INP, d = gtid - (gtid / INP) * INP;
            __nv_bfloat16 hb = __float2bfloat16(xv);
            __nv_bfloat16 lb = __float2bfloat16(xv - __bfloat162float(hb));
            *(__nv_bfloat16*)(smc + OFF_A + grp * GSTRIDE + nxt * ABUF + bb * KSB + (100 + d) * 2) = hb;
            *(__nv_bfloat16*)(smc + OFF_A + grp * GSTRIDE + nxt * ABUF + 3840 + bb * KSB + (100 + d) * 2) = lb;
        }
        asm volatile("bar.sync %0, %1;" :: "r"(barid), "n"(256) : "memory");

        // ---- (mode0) coalesced copy of this step's h hi/lo to global ----
        if (mode == 0) {
            const char* st = smc + OFF_A + grp * GSTRIDE + nxt * ABUF;
            for (int i = gtid; i < 800; i += 256) {
                int arr = (i >= 400);
                int idx = i - arr * 400;
                int row = idx / 25, c8 = idx - row * 25;
                uint2 v = *(const uint2*)(st + arr * 3840 + row * KSB + c8 * 8);
                size_t gr = ((size_t)tg * B + bg0 + row) * KPAD + dir * 100 + c8 * 4;
                *(uint2*)((arr ? g_Al : g_Ah) + gr) = v;
            }
        }
    }
}

// ============================================================================
// conv_b: W_ih_l1f -> bf16 hi/lo, rows gate-interleaved (n' = j*4+gate).
// ============================================================================
__global__ void conv_b_kernel(const float* __restrict__ wih)
{
    int i = blockIdx.x * 256 + threadIdx.x;
    if (i < 400 * 200) {
        int r = i / 200, k = i - r * 200;
        int np = (r % 100) * 4 + r / 100;
        float w = wih[i];
        __nv_bfloat16 hb = __float2bfloat16(w);
        __nv_bfloat16 lb = __float2bfloat16(w - __bfloat162float(hb));
        g_Bh[np * KPAD + k] = hb;
        g_Bl[np * KPAD + k] = lb;
    }
}

// ============================================================================
// xg1 GEMM via mma.sync bf16 (split hi/lo, 3 products); gate-interleaved
// output. grid (5, 1024): 5 CTAs sharing an A m-tile are launch-adjacent.
// ============================================================================
__global__ void __launch_bounds__(256, 2) gemm_xg1_mma(
    const float* __restrict__ bih, const float* __restrict__ bhh)
{
    __shared__ __align__(16) __nv_bfloat16 Asm[2][128][24];
    __shared__ __align__(16) __nv_bfloat16 Bsm[2][80][24];
    __shared__ float bsm[400];

    const int tid  = threadIdx.x;
    const int wid  = tid >> 5;
    const int lane = tid & 31;
    const int n0   = blockIdx.x * 80;
    const int m0   = blockIdx.y * 128;
    const int wm   = (wid >> 1) * 32;
    const int wn   = (wid & 1) * 40;

    for (int i = tid; i < 400; i += 256) {
        int r = (i & 3) * 100 + (i >> 2);
        bsm[i] = bih[r] + bhh[r];
    }

    float acc[2][5][4];
    #pragma unroll
    for (int mt = 0; mt < 2; mt++)
        #pragma unroll
        for (int nt = 0; nt < 5; nt++)
            #pragma unroll
            for (int e = 0; e < 4; e++) acc[mt][nt][e] = 0.f;

    const int arow = tid >> 1, ahalf = tid & 1;
    const int brow = tid >> 1, bhalf = tid & 1;

    uint4 areg = *(const uint4*)(g_Ah + (size_t)(m0 + arow) * KPAD + ahalf * 8);
    uint4 breg = make_uint4(0, 0, 0, 0);
    if (tid < 160) breg = *(const uint4*)(g_Bh + (size_t)(n0 + brow) * KPAD + bhalf * 8);
    *(uint4*)&Asm[0][arow][ahalf * 8] = areg;
    if (tid < 160) *(uint4*)&Bsm[0][brow][bhalf * 8] = breg;
    __syncthreads();

    const uint32_t a_base = smem_u32(&Asm[0][0][0]);
    const uint32_t b_base = smem_u32(&Bsm[0][0][0]);

    for (int it = 0; it < 39; it++) {
        const int cur = it & 1, nxt = cur ^ 1;
        if (it < 38) {
            const int it2 = it + 1;
            const int seg = it2 / 13, kc = it2 - seg * 13;
            const __nv_bfloat16* Ap = (seg == 1) ? g_Al : g_Ah;
            const __nv_bfloat16* Bp = (seg == 2) ? g_Bl : g_Bh;
            areg = *(const uint4*)(Ap + (size_t)(m0 + arow) * KPAD + kc * 16 + ahalf * 8);
            if (tid < 160)
                breg = *(const uint4*)(Bp + (size_t)(n0 + brow) * KPAD + kc * 16 + bhalf * 8);
        }
        const uint32_t abuf = a_base + cur * (128 * 24 * 2);
        const uint32_t bbuf = b_base + cur * (80 * 24 * 2);

        uint32_t af[2][4];
        #pragma unroll
        for (int mt = 0; mt < 2; mt++) {
            uint32_t addr = abuf + (wm + mt * 16 + (lane & 15)) * 48 + (lane >> 4) * 16;
            asm volatile("ldmatrix.sync.aligned.m8n8.x4.shared.b16 {%0,%1,%2,%3}, [%4];"
                : "=r"(af[mt][0]), "=r"(af[mt][1]), "=r"(af[mt][2]), "=r"(af[mt][3])
                : "r"(addr));
        }
        uint32_t bf[5][2];
        #pragma unroll
        for (int nt = 0; nt < 5; nt++) {
            uint32_t addr = bbuf + (wn + nt * 8 + (lane & 7)) * 48 + ((lane >> 3) & 1) * 16;
            asm volatile("ldmatrix.sync.aligned.m8n8.x2.shared.b16 {%0,%1}, [%2];"
                : "=r"(bf[nt][0]), "=r"(bf[nt][1]) : "r"(addr));
        }
        #pragma unroll
        for (int mt = 0; mt < 2; mt++)
            #pragma unroll
            for (int nt = 0; nt < 5; nt++) {
                MMA_BF16(acc[mt][nt], af[mt][0], af[mt][1], af[mt][2], af[mt][3],
                         bf[nt][0], bf[nt][1]);
            }
        if (it < 38) {
            *(uint4*)&Asm[nxt][arow][ahalf * 8] = areg;
            if (tid < 160) *(uint4*)&Bsm[nxt][brow][bhalf * 8] = breg;
        }
        __syncthreads();
    }

    const int gid = lane >> 2, t4 = lane & 3;
    #pragma unroll
    for (int mt = 0; mt < 2; mt++) {
        #pragma unroll
        for (int nt = 0; nt < 5; nt++) {
            int mrow = m0 + wm + mt * 16 + gid;
            int ncol = n0 + wn + nt * 8 + t4 * 2;
            float by = bsm[ncol + 1];
            float2 v0 = make_float2(acc[mt][nt][0] + bsm[ncol], acc[mt][nt][1] + by);
            float2 v1 = make_float2(acc[mt][nt][2] + bsm[ncol], acc[mt][nt][3] + by);
            *(float2*)&g_xg1[(size_t)mrow * 400 + ncol]       = v0;
            *(float2*)&g_xg1[(size_t)(mrow + 8) * 400 + ncol] = v1;
        }
    }
}

// ============================================================================
// lstm_final: layer1 backward single step (c0=0) + FC + softmax. (unchanged)
// ============================================================================
#define FN_SMEMF (30000 + 200*18 + 1600 + 300 + 600 + 4 + 48)

__global__ void __launch_bounds__(256, 1) lstm_final(
    const float* __restrict__ wih1b,
    const float* __restrict__ bih1b, const float* __restrict__ bhh1b,
    const float* __restrict__ fc_w,  const float* __restrict__ fc_b,
    float* __restrict__ out)
{
    extern __shared__ float sm[];
    float* wT   = sm;
    float* h0s  = sm + 30000;
    float* h1bs = sm + 33600;
    float* b3   = sm + 35200;
    float* fcw  = sm + 35500;
    float* fcb  = sm + 36100;
    float* lg   = sm + 36104;

    const int tid = threadIdx.x;
    const int b0 = blockIdx.x * 16;

    for (int i = tid; i < 16 * 200; i += 256) {
        int b = i / 200, k = i - b * 200;
        h0s[k * 18 + b] = g_h0s[(size_t)(b0 + b) * 200 + k];
    }
    for (int i = tid; i < 300; i += 256) {
        int g3 = i / 100, j = i - g3 * 100;
        int row = j + (g3 == 0 ? 0 : (g3 == 1 ? 200 : 300));
        b3[i] = bih1b[row] + bhh1b[row];
    }
    for (int i = tid; i < 600; i += 256) fcw[i] = fc_w[i];
    if (tid < 3) fcb[tid] = fc_b[tid];

    const int  jj  = tid & 127;
    const int  grp = tid >> 7;
    const bool act = (jj < H);

    u64 acc[4][3];
    #pragma unroll
    for (int p = 0; p < 4; p++)
        #pragma unroll
        for (int g = 0; g < 3; g++) acc[p][g] = pk2(0.f, 0.f);

    for (int kt = 0; kt < 2; kt++) {
        __syncthreads();
        for (int i = tid; i < 30000; i += 256) {
            int k = i % 100, j100 = i / 100;
            int grow = j100 + (j100 >= 100 ? 100 : 0);
            wT[k * 300 + j100] = wih1b[(size_t)grow * 200 + kt * 100 + k];
        }
        __syncthreads();
        if (act) {
            #pragma unroll 2
            for (int k = 0; k < 100; k++) {
                const float* wr = wT + k * 300 + jj;
                u64 w0 = pk2(wr[0], wr[0]);
                u64 w1 = pk2(wr[100], wr[100]);
                u64 w2 = pk2(wr[200], wr[200]);
                const float* hb = h0s + (kt * 100 + k) * 18 + grp * 8;
                #pragma unroll
                for (int p = 0; p < 4; p++) {
                    u64 hv = *(const u64*)(hb + 2 * p);
                    acc[p][0] = ffma2(w0, hv, acc[p][0]);
                    acc[p][1] = ffma2(w1, hv, acc[p][1]);
                    acc[p][2] = ffma2(w2, hv, acc[p][2]);
                }
            }
        }
    }
    if (act) {
        #pragma unroll
        for (int p = 0; p < 4; p++) {
            float i0, i1, g0, g1, o0, o1;
            upk2(acc[p][0], i0, i1);
            upk2(acc[p][1], g0, g1);
            upk2(acc[p][2], o0, o1);
            float bi = b3[jj], bg = b3[100 + jj], bo = b3[200 + jj];
            i0 += bi; i1 += bi; g0 += bg; g1 += bg; o0 += bo; o1 += bo;
            float c0 = fsig(i0) * ftanh_(g0);
            float c1 = fsig(i1) * ftanh_(g1);
            int bl = grp * 8 + 2 * p;
            h1bs[bl * 100 + jj]       = fsig(o0) * ftanh_(c0);
            h1bs[(bl + 1) * 100 + jj] = fsig(o1) * ftanh_(c1);
        }
    }
    __syncthreads();
    if (tid < 48) {
        int b = tid / 3, cls = tid - b * 3;
        float a = fcb[cls];
        const float* h1f = g_h1f + (size_t)(b0 + b) * 100;
        #pragma unroll 4
        for (int j = 0; j < 100; j++) {
            a += h1f[j]            * fcw[cls * 200 + j];
            a += h1bs[b * 100 + j] * fcw[cls * 200 + 100 + j];
        }
        lg[tid] = a;
    }
    __syncthreads();
    if (tid < 16) {
        int b = tid;
        float l0 = lg[b * 3], l1 = lg[b * 3 + 1], l2 = lg[b * 3 + 2];
        float m = fmaxf(l0, fmaxf(l1, l2));
        float e0 = __expf(l0 - m), e1 = __expf(l1 - m), e2 = __expf(l2 - m);
        float s = 1.0f / (e0 + e1 + e2);
        out[(b0 + b) * 3 + 0] = e0 * s;
        out[(b0 + b) * 3 + 1] = e1 * s;
        out[(b0 + b) * 3 + 2] = e2 * s;
    }
}

// ============================================================================
extern "C" void kernel_launch(void* const* d_in, const int* in_sizes, int n_in,
                              void* d_out, int out_size)
{
    (void)in_sizes; (void)n_in; (void)out_size;
    const float* x     = (const float*)d_in[0];
    const float* wih0f = (const float*)d_in[1];
    const float* whh0f = (const float*)d_in[2];
    const float* bih0f = (const float*)d_in[3];
    const float* bhh0f = (const float*)d_in[4];
    const float* wih0b = (const float*)d_in[5];
    const float* whh0b = (const float*)d_in[6];
    const float* bih0b = (const float*)d_in[7];
    const float* bhh0b = (const float*)d_in[8];
    const float* wih1f = (const float*)d_in[9];
    const float* whh1f = (const float*)d_in[10];
    const float* bih1f = (const float*)d_in[11];
    const float* bhh1f = (const float*)d_in[12];
    const float* wih1b = (const float*)d_in[13];
    const float* bih1b = (const float*)d_in[15];
    const float* bhh1b = (const float*)d_in[16];
    const float* fcw   = (const float*)d_in[17];
    const float* fcb   = (const float*)d_in[18];
    float* out = (float*)d_out;

    float* xg1p; cudaGetSymbolAddress((void**)&xg1p, g_xg1);

    cudaFuncSetAttribute(lstm_rec_mma, cudaFuncAttributeMaxDynamicSharedMemorySize, RC_SMEM);
    cudaFuncSetAttribute(lstm_final,   cudaFuncAttributeMaxDynamicSharedMemorySize, FN_SMEMF * 4);

    conv_b_kernel<<<(400 * 200 + 255) / 256, 256>>>(wih1f);
    lstm_rec_mma<<<64, NTHR, RC_SMEM>>>(nullptr, x, whh0f, whh0b, wih0f, wih0b,
                                        bih0f, bhh0f, bih0b, bhh0b, 0);
    gemm_xg1_mma<<<dim3(5, 1024), 256>>>(bih1f, bhh1f);
    lstm_rec_mma<<<32, NTHR, RC_SMEM>>>(xg1p, nullptr, whh1f, whh1f, wih1f, wih1f,
                                        bih1f, bhh1f, bih1f, bhh1f, 1);
    lstm_final<<<64, 256, FN_SMEMF * 4>>>(wih1b, bih1b, bhh1b, fcw, fcb, out);
}

// round 12
// speedup vs baseline: 1.4046x; 1.4046x over previous
#include <cuda_runtime.h>
#include <cuda_bf16.h>
#include <cstdint>

#define B 1024
#define T 128
#define INP 5
#define H 100
#define G4 400
#define MTOT (B*T)
#define KPAD 256          // k-stride of bf16 A/B arrays; 128B-aligned k-slices

// ---------------- scratch (device globals; no runtime allocation) ----------
__device__ float g_h0s[B * 2 * H];            // [b][200] h0 at t=T-1
__device__ float g_xg1[(size_t)MTOT * G4];    // [t*B+b][n'] layer1-fwd gates (+bias), gate-interleaved
__device__ float g_h1f[B * H];
__device__ __nv_bfloat16 g_Ah[(size_t)MTOT * KPAD];   // h0 hi, [t*B+b][k]; cols 200..255 = 0
__device__ __nv_bfloat16 g_Al[(size_t)MTOT * KPAD];
__device__ __nv_bfloat16 g_Bh[400 * KPAD];            // W_ih_l1f rows gate-interleaved
__device__ __nv_bfloat16 g_Bl[400 * KPAD];

typedef unsigned long long u64;

__device__ __forceinline__ u64 pk2(float a, float b) {
    u64 r; asm("mov.b64 %0, {%1,%2};" : "=l"(r) : "f"(a), "f"(b)); return r;
}
__device__ __forceinline__ void upk2(u64 v, float& a, float& b) {
    asm("mov.b64 {%0,%1}, %2;" : "=f"(a), "=f"(b) : "l"(v));
}
__device__ __forceinline__ u64 ffma2(u64 a, u64 b, u64 c) {
    asm("fma.rn.f32x2 %0, %1, %2, %0;" : "+l"(c) : "l"(a), "l"(b)); return c;
}
__device__ __forceinline__ float fsig(float x) {
    float e; asm("ex2.approx.f32 %0, %1;" : "=f"(e) : "f"(x * -1.4426950408889634f));
    float r; asm("rcp.approx.f32 %0, %1;" : "=f"(r) : "f"(e + 1.0f));
    return r;
}
__device__ __forceinline__ float ftanh_(float x) {
    float e; asm("ex2.approx.f32 %0, %1;" : "=f"(e) : "f"(x * -2.885390081777927f));
    float r; asm("rcp.approx.f32 %0, %1;" : "=f"(r) : "f"(e + 1.0f));
    return fmaf(2.0f, r, -1.0f);
}
__device__ __forceinline__ uint32_t smem_u32(const void* p) {
    uint32_t a;
    asm("{ .reg .u64 t; cvta.to.shared.u64 t, %1; cvt.u32.u64 %0, t; }" : "=r"(a) : "l"(p));
    return a;
}

#define MMA_BF16(ac, a0,a1,a2,a3, b0,b1) \
    asm volatile("mma.sync.aligned.m16n8k16.row.col.f32.bf16.bf16.f32 " \
        "{%0,%1,%2,%3}, {%4,%5,%6,%7}, {%8,%9}, {%0,%1,%2,%3};" \
        : "+f"((ac)[0]), "+f"((ac)[1]), "+f"((ac)[2]), "+f"((ac)[3]) \
        : "r"(a0), "r"(a1), "r"(a2), "r"(a3), "r"(b0), "r"(b1))

// ============================================================================
// TENSOR-CORE RECURRENCE (R10 config: 16 batches/CTA, 512 thr / 16 warps,
// 4 n-tile slots/warp, gate-interleaved n'=j*4+gate, ONE barrier/step).
// mode 0: layer0 (grid 128: dir=bid>>6), h hi/lo copied to global COALESCED
//         after the barrier (uint2, replaces scattered 2B stores) + g_h0s.
// mode 1: layer1 fwd (grid 64), acc init from g_xg1, emits g_h1f.
// SMEM: Wh[400][120] | Wl | A bufs x2 (Ah[16][120] + Al)
// ============================================================================
#define KSB     240
#define OFF_WL  96000
#define OFF_A   192000
#define ABUF    7680
#define RC_SMEM 207360
#define NTHR    512

__global__ void __launch_bounds__(NTHR, 1) lstm_rec_mma(
    const float* __restrict__ xg,
    const float* __restrict__ x,
    const float* __restrict__ whf, const float* __restrict__ whb,
    const float* __restrict__ wihf, const float* __restrict__ wihb,
    const float* __restrict__ bihf, const float* __restrict__ bhhf,
    const float* __restrict__ bihb, const float* __restrict__ bhhb,
    int mode)
{
    extern __shared__ char smc[];
    const uint32_t sb = smem_u32(smc);
    const int tid = threadIdx.x, wid = tid >> 5, lane = tid & 31;
    const int g = lane >> 2, t4 = lane & 3;
    const int dir = (mode == 0) ? (int)(blockIdx.x >> 6) : 0;
    const int b0  = (mode == 0) ? (int)(blockIdx.x & 63) * 16 : (int)blockIdx.x * 16;
    const float* wp  = dir ? whb  : whf;
    const float* wip = dir ? wihb : wihf;
    const float* bi_ = dir ? bihb : bihf;
    const float* bh_ = dir ? bhhb : bhhf;

    // zero everything (W pads, A pads, h=0 initial state)
    for (int i = tid; i < (RC_SMEM >> 4); i += NTHR)
        ((uint4*)smc)[i] = make_uint4(0, 0, 0, 0);
    __syncthreads();
    // W fill: row n' = j*4+gate <- orig row gate*100+j ; k 0..99 = Whh
    for (int i = tid; i < 400 * 100; i += NTHR) {
        int r = i / 100, k = i - r * 100;
        int np = (r % 100) * 4 + r / 100;
        float w = wp[i];
        __nv_bfloat16 hb = __float2bfloat16(w);
        __nv_bfloat16 lb = __float2bfloat16(w - __bfloat162float(hb));
        *(__nv_bfloat16*)(smc + np * KSB + k * 2) = hb;
        *(__nv_bfloat16*)(smc + OFF_WL + np * KSB + k * 2) = lb;
    }
    if (mode == 0) {
        for (int i = tid; i < 400 * INP; i += NTHR) {
            int r = i / INP, d = i - r * INP;
            int np = (r % 100) * 4 + r / 100;
            float w = wip[i];
            __nv_bfloat16 hb = __float2bfloat16(w);
            __nv_bfloat16 lb = __float2bfloat16(w - __bfloat162float(hb));
            *(__nv_bfloat16*)(smc + np * KSB + (100 + d) * 2) = hb;
            *(__nv_bfloat16*)(smc + OFF_WL + np * KSB + (100 + d) * 2) = lb;
        }
        if (tid < 16 * INP) {
            int bb = tid / INP, d = tid - (tid / INP) * INP;
            int tg0 = dir ? (T - 1) : 0;
            float xv = x[((size_t)(b0 + bb) * T + tg0) * INP + d];
            __nv_bfloat16 hb = __float2bfloat16(xv);
            __nv_bfloat16 lb = __float2bfloat16(xv - __bfloat162float(hb));
            *(__nv_bfloat16*)(smc + OFF_A + bb * KSB + (100 + d) * 2) = hb;
            *(__nv_bfloat16*)(smc + OFF_A + 3840 + bb * KSB + (100 + d) * 2) = lb;
        }
    }

    // 4 slots/warp: tile = wid + 16*i, valid if < 50 (dummies -> tile 0)
    int  tl[4]; bool tv[4];
    float br[4][2];
    #pragma unroll
    for (int i = 0; i < 4; i++) {
        int t = wid + 16 * i;
        tv[i] = (t < 50); tl[i] = tv[i] ? t : 0;
        br[i][0] = br[i][1] = 0.f;
        if (mode == 0 && tv[i]) {
            int np = t * 8 + 2 * t4;
            int r0 = (np & 3) * 100 + (np >> 2);
            int r1 = ((np + 1) & 3) * 100 + ((np + 1) >> 2);
            br[i][0] = bi_[r0] + bh_[r0];
            br[i][1] = bi_[r1] + bh_[r1];
        }
    }
    float cst[4];
    #pragma unroll
    for (int i = 0; i < 4; i++) cst[i] = 0.f;

    float xp[4][4];
    if (mode == 1) {
        #pragma unroll
        for (int i = 0; i < 4; i++) {
            xp[i][0] = xp[i][1] = xp[i][2] = xp[i][3] = 0.f;
            if (tv[i]) {
                const float* p0 = xg + (size_t)(b0 + g) * 400 + tl[i] * 8 + 2 * t4;
                float2 v0 = *(const float2*)p0;
                float2 v1 = *(const float2*)(p0 + 3200);
                xp[i][0] = v0.x; xp[i][1] = v0.y; xp[i][2] = v1.x; xp[i][3] = v1.y;
            }
        }
    }
    __syncthreads();

    for (int ts = 0; ts < T; ts++) {
        const int cur = ts & 1, nxt = cur ^ 1;
        const int tg = dir ? (T - 1 - ts) : ts;

        float acc[4][4];
        if (mode == 0) {
            #pragma unroll
            for (int i = 0; i < 4; i++) {
                acc[i][0] = br[i][0]; acc[i][1] = br[i][1];
                acc[i][2] = br[i][0]; acc[i][3] = br[i][1];
            }
        } else {
            #pragma unroll
            for (int i = 0; i < 4; i++) {
                acc[i][0] = xp[i][0]; acc[i][1] = xp[i][1];
                acc[i][2] = xp[i][2]; acc[i][3] = xp[i][3];
            }
            if (ts + 1 < T) {
                #pragma unroll
                for (int i = 0; i < 4; i++) {
                    if (tv[i]) {
                        const float* p0 = xg + ((size_t)(ts + 1) * B + b0 + g) * 400 + tl[i] * 8 + 2 * t4;
                        float2 v0 = *(const float2*)p0;
                        float2 v1 = *(const float2*)(p0 + 3200);
                        xp[i][0] = v0.x; xp[i][1] = v0.y; xp[i][2] = v1.x; xp[i][3] = v1.y;
                    }
                }
            }
        }
        float xv = 0.f;
        if (mode == 0 && tid < 16 * INP && ts + 1 < T) {
            int bb = tid / INP, d = tid - (tid / INP) * INP;
            int tgn = dir ? (tg - 1) : (tg + 1);
            xv = x[((size_t)(b0 + bb) * T + tgn) * INP + d];
        }

        // ---- MMA: 7 k-chunks x 4 slots x 3 split products (product-outer) ----
        const uint32_t aBase = sb + OFF_A + cur * ABUF;
        #pragma unroll
        for (int kc = 0; kc < 7; kc++) {
            uint32_t ah[4], al[4];
            uint32_t aa = aBase + (lane & 15) * KSB + (lane >> 4) * 16 + kc * 32;
            asm volatile("ldmatrix.sync.aligned.m8n8.x4.shared.b16 {%0,%1,%2,%3}, [%4];"
                : "=r"(ah[0]), "=r"(ah[1]), "=r"(ah[2]), "=r"(ah[3]) : "r"(aa));
            asm volatile("ldmatrix.sync.aligned.m8n8.x4.shared.b16 {%0,%1,%2,%3}, [%4];"
                : "=r"(al[0]), "=r"(al[1]), "=r"(al[2]), "=r"(al[3]) : "r"(aa + 3840));

            uint32_t wh[4][2], wl[4][2];
            #pragma unroll
            for (int p = 0; p < 2; p++) {
                int m = lane >> 3;
                int tt = tl[2 * p + (m >> 1)];
                uint32_t wa = sb + (8 * tt + (lane & 7)) * KSB + (m & 1) * 16 + kc * 32;
                asm volatile("ldmatrix.sync.aligned.m8n8.x4.shared.b16 {%0,%1,%2,%3}, [%4];"
                    : "=r"(wh[2*p][0]), "=r"(wh[2*p][1]), "=r"(wh[2*p+1][0]), "=r"(wh[2*p+1][1])
                    : "r"(wa));
                asm volatile("ldmatrix.sync.aligned.m8n8.x4.shared.b16 {%0,%1,%2,%3}, [%4];"
                    : "=r"(wl[2*p][0]), "=r"(wl[2*p][1]), "=r"(wl[2*p+1][0]), "=r"(wl[2*p+1][1])
                    : "r"(wa + OFF_WL));
            }
            #pragma unroll
            for (int i = 0; i < 4; i++)
                MMA_BF16(acc[i], ah[0], ah[1], ah[2], ah[3], wh[i][0], wh[i][1]);
            #pragma unroll
            for (int i = 0; i < 4; i++)
                MMA_BF16(acc[i], al[0], al[1], al[2], al[3], wh[i][0], wh[i][1]);
            #pragma unroll
            for (int i = 0; i < 4; i++)
                MMA_BF16(acc[i], ah[0], ah[1], ah[2], ah[3], wl[i][0], wl[i][1]);
        }

        // ---- gate exchange + in-register activations ----
        #pragma unroll
        for (int i = 0; i < 4; i++) {
            if (tv[i]) {
                float s0 = __shfl_xor_sync(0xffffffffu, acc[i][0], 1);
                float s1 = __shfl_xor_sync(0xffffffffu, acc[i][1], 1);
                float s2 = __shfl_xor_sync(0xffffffffu, acc[i][2], 1);
                float s3 = __shfl_xor_sync(0xffffffffu, acc[i][3], 1);
                bool odd = (t4 & 1);
                float gi = odd ? s2 : acc[i][0];
                float gf = odd ? s3 : acc[i][1];
                float gg = odd ? acc[i][2] : s0;
                float go = odd ? acc[i][3] : s1;
                float cv = fsig(gf) * cst[i] + fsig(gi) * ftanh_(gg);
                cst[i] = cv;
                float h = fsig(go) * ftanh_(cv);
                __nv_bfloat16 hh = __float2bfloat16(h);
                __nv_bfloat16 hl = __float2bfloat16(h - __bfloat162float(hh));
                int bu = g + (odd ? 8 : 0);
                int ju = 2 * tl[i] + (t4 >> 1);
                uint32_t off = OFF_A + nxt * ABUF + bu * KSB + ju * 2;
                *(__nv_bfloat16*)(smc + off) = hh;
                *(__nv_bfloat16*)(smc + off + 3840) = hl;
                if (mode == 0) {
                    if (tg == T - 1)
                        g_h0s[(size_t)(b0 + bu) * 200 + dir * 100 + ju] = h;
                } else if (ts == T - 1) {
                    g_h1f[(size_t)(b0 + bu) * 100 + ju] = h;
                }
            }
        }
        if (mode == 0 && tid < 16 * INP && ts + 1 < T) {
            int bb = tid / INP, d = tid - (tid / INP) * INP;
            __nv_bfloat16 hb = __float2bfloat16(xv);
            __nv_bfloat16 lb = __float2bfloat16(xv - __bfloat162float(hb));
            *(__nv_bfloat16*)(smc + OFF_A + nxt * ABUF + bb * KSB + (100 + d) * 2) = hb;
            *(__nv_bfloat16*)(smc + OFF_A + nxt * ABUF + 3840 + bb * KSB + (100 + d) * 2) = lb;
        }
        __syncthreads();

        // ---- (mode0) coalesced copy of this step's h hi/lo to global ----
        // reads buf[nxt] (written above); next step's MMA reads it too (no hazard)
        if (mode == 0) {
            const char* st = smc + OFF_A + nxt * ABUF;
            for (int i = tid; i < 800; i += NTHR) {
                int arr = (i >= 400);
                int idx = i - arr * 400;
                int row = idx / 25, c8 = idx - row * 25;
                uint2 v = *(const uint2*)(st + arr * 3840 + row * KSB + c8 * 8);
                size_t gr = ((size_t)tg * B + b0 + row) * KPAD + dir * 100 + c8 * 4;
                *(uint2*)((arr ? g_Al : g_Ah) + gr) = v;
            }
        }
    }
}

// ============================================================================
// conv_b: W_ih_l1f -> bf16 hi/lo, rows gate-interleaved (n' = j*4+gate).
// ============================================================================
__global__ void conv_b_kernel(const float* __restrict__ wih)
{
    int i = blockIdx.x * 256 + threadIdx.x;
    if (i < 400 * 200) {
        int r = i / 200, k = i - r * 200;
        int np = (r % 100) * 4 + r / 100;
        float w = wih[i];
        __nv_bfloat16 hb = __float2bfloat16(w);
        __nv_bfloat16 lb = __float2bfloat16(w - __bfloat162float(hb));
        g_Bh[np * KPAD + k] = hb;
        g_Bl[np * KPAD + k] = lb;
    }
}

// ============================================================================
// xg1 GEMM (REBUILT): BM=128, BN=80, BK=64, 12 iters (3 segs x 4 k-chunks of
// KPAD=256). A k-slices are 128B-aligned full cache lines -> 100% line
// efficiency. Dynamic smem 61.5KB double-buffered; 72-el row stride
// (36-word stride -> conflict-free ldmatrix). grid (5, 1024).
// ============================================================================
#define GRS   72                          // smem row stride (elements)
#define GA_B  (128 * GRS * 2)             // one A buffer: 18,432 B
#define GB_B  (80 * GRS * 2)              // one B buffer: 11,520 B
#define GOFF_B  (2 * GA_B)                // 36,864
#define GOFF_BI (2 * GA_B + 2 * GB_B)     // 59,904
#define GSMEM   (GOFF_BI + 1600)          // 61,504 B

__global__ void __launch_bounds__(256) gemm_xg1_mma(
    const float* __restrict__ bih, const float* __restrict__ bhh)
{
    extern __shared__ char gsm[];
    const uint32_t sbase = smem_u32(gsm);
    float* bsm = (float*)(gsm + GOFF_BI);

    const int tid  = threadIdx.x;
    const int wid  = tid >> 5;
    const int lane = tid & 31;
    const int n0   = blockIdx.x * 80;
    const int m0   = blockIdx.y * 128;
    const int wm   = (wid >> 1) * 32;
    const int wn   = (wid & 1) * 40;

    for (int i = tid; i < 400; i += 256) {
        int r = (i & 3) * 100 + (i >> 2);
        bsm[i] = bih[r] + bhh[r];
    }

    float acc[2][5][4];
    #pragma unroll
    for (int mt = 0; mt < 2; mt++)
        #pragma unroll
        for (int nt = 0; nt < 5; nt++)
            #pragma unroll
            for (int e = 0; e < 4; e++) acc[mt][nt][e] = 0.f;

    const int arow = tid >> 1, ahalf = tid & 1;   // 2 thr/row, 64B each
    const int brow = tid >> 1, bhalf = tid & 1;   // tid<160: 80 B rows

    // preload iter 0 (seg 0 = Ah*Bh, k-chunk 0)
    uint4 ar[4], brg[4];
    {
        const uint4* ap = (const uint4*)(g_Ah + (size_t)(m0 + arow) * KPAD + ahalf * 32);
        #pragma unroll
        for (int i = 0; i < 4; i++) ar[i] = ap[i];
        if (tid < 160) {
            const uint4* bp = (const uint4*)(g_Bh + (size_t)(n0 + brow) * KPAD + bhalf * 32);
            #pragma unroll
            for (int i = 0; i < 4; i++) brg[i] = bp[i];
        }
    }
    {
        char* ad = gsm + arow * (GRS * 2) + ahalf * 64;
        #pragma unroll
        for (int i = 0; i < 4; i++) *(uint4*)(ad + i * 16) = ar[i];
        if (tid < 160) {
            char* bd = gsm + GOFF_B + brow * (GRS * 2) + bhalf * 64;
            #pragma unroll
            for (int i = 0; i < 4; i++) *(uint4*)(bd + i * 16) = brg[i];
        }
    }
    __syncthreads();

    for (int it = 0; it < 12; it++) {
        const int cur = it & 1, nxt = cur ^ 1;
        if (it < 11) {
            const int it2 = it + 1;
            const int seg = it2 >> 2, kc = it2 & 3;
            const __nv_bfloat16* Ap = (seg == 1) ? g_Al : g_Ah;
            const __nv_bfloat16* Bp = (seg == 2) ? g_Bl : g_Bh;
            const uint4* ap = (const uint4*)(Ap + (size_t)(m0 + arow) * KPAD + kc * 64 + ahalf * 32);
            #pragma unroll
            for (int i = 0; i < 4; i++) ar[i] = ap[i];
            if (tid < 160) {
                const uint4* bp = (const uint4*)(Bp + (size_t)(n0 + brow) * KPAD + kc * 64 + bhalf * 32);
                #pragma unroll
                for (int i = 0; i < 4; i++) brg[i] = bp[i];
            }
        }

        const uint32_t abuf = sbase + cur * GA_B;
        const uint32_t bbuf = sbase + GOFF_B + cur * GB_B;
        #pragma unroll
        for (int kk = 0; kk < 4; kk++) {
            uint32_t af[2][4];
            #pragma unroll
            for (int mt = 0; mt < 2; mt++) {
                uint32_t addr = abuf + (wm + mt * 16 + (lane & 15)) * (GRS * 2)
                              + (lane >> 4) * 16 + kk * 32;
                asm volatile("ldmatrix.sync.aligned.m8n8.x4.shared.b16 {%0,%1,%2,%3}, [%4];"
                    : "=r"(af[mt][0]), "=r"(af[mt][1]), "=r"(af[mt][2]), "=r"(af[mt][3])
                    : "r"(addr));
            }
            uint32_t bf[5][2];
            #pragma unroll
            for (int nt = 0; nt < 5; nt++) {
                uint32_t addr = bbuf + (wn + nt * 8 + (lane & 7)) * (GRS * 2)
                              + ((lane >> 3) & 1) * 16 + kk * 32;
                asm volatile("ldmatrix.sync.aligned.m8n8.x2.shared.b16 {%0,%1}, [%2];"
                    : "=r"(bf[nt][0]), "=r"(bf[nt][1]) : "r"(addr));
            }
            #pragma unroll
            for (int mt = 0; mt < 2; mt++)
                #pragma unroll
                for (int nt = 0; nt < 5; nt++)
                    MMA_BF16(acc[mt][nt], af[mt][0], af[mt][1], af[mt][2], af[mt][3],
                             bf[nt][0], bf[nt][1]);
        }

        if (it < 11) {
            char* ad = gsm + nxt * GA_B + arow * (GRS * 2) + ahalf * 64;
            #pragma unroll
            for (int i = 0; i < 4; i++) *(uint4*)(ad + i * 16) = ar[i];
            if (tid < 160) {
                char* bd = gsm + GOFF_B + nxt * GB_B + brow * (GRS * 2) + bhalf * 64;
                #pragma unroll
                for (int i = 0; i < 4; i++) *(uint4*)(bd + i * 16) = brg[i];
            }
        }
        __syncthreads();
    }

    const int gid = lane >> 2, t4 = lane & 3;
    #pragma unroll
    for (int mt = 0; mt < 2; mt++) {
        #pragma unroll
        for (int nt = 0; nt < 5; nt++) {
            int mrow = m0 + wm + mt * 16 + gid;
            int ncol = n0 + wn + nt * 8 + t4 * 2;
            float by = bsm[ncol + 1];
            float2 v0 = make_float2(acc[mt][nt][0] + bsm[ncol], acc[mt][nt][1] + by);
            float2 v1 = make_float2(acc[mt][nt][2] + bsm[ncol], acc[mt][nt][3] + by);
            *(float2*)&g_xg1[(size_t)mrow * 400 + ncol]       = v0;
            *(float2*)&g_xg1[(size_t)(mrow + 8) * 400 + ncol] = v1;
        }
    }
}

// ============================================================================
// lstm_final: layer1 backward single step (c0=0) + FC + softmax. (unchanged)
// ============================================================================
#define FN_SMEMF (30000 + 200*18 + 1600 + 300 + 600 + 4 + 48)

__global__ void __launch_bounds__(256, 1) lstm_final(
    const float* __restrict__ wih1b,
    const float* __restrict__ bih1b, const float* __restrict__ bhh1b,
    const float* __restrict__ fc_w,  const float* __restrict__ fc_b,
    float* __restrict__ out)
{
    extern __shared__ float sm[];
    float* wT   = sm;
    float* h0s  = sm + 30000;
    float* h1bs = sm + 33600;
    float* b3   = sm + 35200;
    float* fcw  = sm + 35500;
    float* fcb  = sm + 36100;
    float* lg   = sm + 36104;

    const int tid = threadIdx.x;
    const int b0 = blockIdx.x * 16;

    for (int i = tid; i < 16 * 200; i += 256) {
        int b = i / 200, k = i - b * 200;
        h0s[k * 18 + b] = g_h0s[(size_t)(b0 + b) * 200 + k];
    }
    for (int i = tid; i < 300; i += 256) {
        int g3 = i / 100, j = i - g3 * 100;
        int row = j + (g3 == 0 ? 0 : (g3 == 1 ? 200 : 300));
        b3[i] = bih1b[row] + bhh1b[row];
    }
    for (int i = tid; i < 600; i += 256) fcw[i] = fc_w[i];
    if (tid < 3) fcb[tid] = fc_b[tid];

    const int  jj  = tid & 127;
    const int  grp = tid >> 7;
    const bool act = (jj < H);

    u64 acc[4][3];
    #pragma unroll
    for (int p = 0; p < 4; p++)
        #pragma unroll
        for (int g = 0; g < 3; g++) acc[p][g] = pk2(0.f, 0.f);

    for (int kt = 0; kt < 2; kt++) {
        __syncthreads();
        for (int i = tid; i < 30000; i += 256) {
            int k = i % 100, j100 = i / 100;
            int grow = j100 + (j100 >= 100 ? 100 : 0);
            wT[k * 300 + j100] = wih1b[(size_t)grow * 200 + kt * 100 + k];
        }
        __syncthreads();
        if (act) {
            #pragma unroll 2
            for (int k = 0; k < 100; k++) {
                const float* wr = wT + k * 300 + jj;
                u64 w0 = pk2(wr[0], wr[0]);
                u64 w1 = pk2(wr[100], wr[100]);
                u64 w2 = pk2(wr[200], wr[200]);
                const float* hb = h0s + (kt * 100 + k) * 18 + grp * 8;
                #pragma unroll
                for (int p = 0; p < 4; p++) {
                    u64 hv = *(const u64*)(hb + 2 * p);
                    acc[p][0] = ffma2(w0, hv, acc[p][0]);
                    acc[p][1] = ffma2(w1, hv, acc[p][1]);
                    acc[p][2] = ffma2(w2, hv, acc[p][2]);
                }
            }
        }
    }
    if (act) {
        #pragma unroll
        for (int p = 0; p < 4; p++) {
            float i0, i1, g0, g1, o0, o1;
            upk2(acc[p][0], i0, i1);
            upk2(acc[p][1], g0, g1);
            upk2(acc[p][2], o0, o1);
            float bi = b3[jj], bg = b3[100 + jj], bo = b3[200 + jj];
            i0 += bi; i1 += bi; g0 += bg; g1 += bg; o0 += bo; o1 += bo;
            float c0 = fsig(i0) * ftanh_(g0);
            float c1 = fsig(i1) * ftanh_(g1);
            int bl = grp * 8 + 2 * p;
            h1bs[bl * 100 + jj]       = fsig(o0) * ftanh_(c0);
            h1bs[(bl + 1) * 100 + jj] = fsig(o1) * ftanh_(c1);
        }
    }
    __syncthreads();
    if (tid < 48) {
        int b = tid / 3, cls = tid - b * 3;
        float a = fcb[cls];
        const float* h1f = g_h1f + (size_t)(b0 + b) * 100;
        #pragma unroll 4
        for (int j = 0; j < 100; j++) {
            a += h1f[j]            * fcw[cls * 200 + j];
            a += h1bs[b * 100 + j] * fcw[cls * 200 + 100 + j];
        }
        lg[tid] = a;
    }
    __syncthreads();
    if (tid < 16) {
        int b = tid;
        float l0 = lg[b * 3], l1 = lg[b * 3 + 1], l2 = lg[b * 3 + 2];
        float m = fmaxf(l0, fmaxf(l1, l2));
        float e0 = __expf(l0 - m), e1 = __expf(l1 - m), e2 = __expf(l2 - m);
        float s = 1.0f / (e0 + e1 + e2);
        out[(b0 + b) * 3 + 0] = e0 * s;
        out[(b0 + b) * 3 + 1] = e1 * s;
        out[(b0 + b) * 3 + 2] = e2 * s;
    }
}

// ============================================================================
extern "C" void kernel_launch(void* const* d_in, const int* in_sizes, int n_in,
                              void* d_out, int out_size)
{
    (void)in_sizes; (void)n_in; (void)out_size;
    const float* x     = (const float*)d_in[0];
    const float* wih0f = (const float*)d_in[1];
    const float* whh0f = (const float*)d_in[2];
    const float* bih0f = (const float*)d_in[3];
    const float* bhh0f = (const float*)d_in[4];
    const float* wih0b = (const float*)d_in[5];
    const float* whh0b = (const float*)d_in[6];
    const float* bih0b = (const float*)d_in[7];
    const float* bhh0b = (const float*)d_in[8];
    const float* wih1f = (const float*)d_in[9];
    const float* whh1f = (const float*)d_in[10];
    const float* bih1f = (const float*)d_in[11];
    const float* bhh1f = (const float*)d_in[12];
    const float* wih1b = (const float*)d_in[13];
    const float* bih1b = (const float*)d_in[15];
    const float* bhh1b = (const float*)d_in[16];
    const float* fcw   = (const float*)d_in[17];
    const float* fcb   = (const float*)d_in[18];
    float* out = (float*)d_out;

    float* xg1p; cudaGetSymbolAddress((void**)&xg1p, g_xg1);

    cudaFuncSetAttribute(lstm_rec_mma,  cudaFuncAttributeMaxDynamicSharedMemorySize, RC_SMEM);
    cudaFuncSetAttribute(gemm_xg1_mma,  cudaFuncAttributeMaxDynamicSharedMemorySize, GSMEM);
    cudaFuncSetAttribute(lstm_final,    cudaFuncAttributeMaxDynamicSharedMemorySize, FN_SMEMF * 4);

    conv_b_kernel<<<(400 * 200 + 255) / 256, 256>>>(wih1f);
    lstm_rec_mma<<<128, NTHR, RC_SMEM>>>(nullptr, x, whh0f, whh0b, wih0f, wih0b,
                                         bih0f, bhh0f, bih0b, bhh0b, 0);
    gemm_xg1_mma<<<dim3(5, 1024), 256, GSMEM>>>(bih1f, bhh1f);
    lstm_rec_mma<<<64, NTHR, RC_SMEM>>>(xg1p, nullptr, whh1f, whh1f, wih1f, wih1f,
                                        bih1f, bhh1f, bih1f, bhh1f, 1);
    lstm_final<<<64, 256, FN_SMEMF * 4>>>(wih1b, bih1b, bhh1b, fcw, fcb, out);
}

// round 13
// speedup vs baseline: 1.5822x; 1.1264x over previous
#include <cuda_runtime.h>
#include <cuda_bf16.h>
#include <cstdint>

#define B 1024
#define T 128
#define INP 5
#define H 100
#define G4 400
#define MTOT (B*T)
#define KPAD 256          // k-stride of bf16 A/B arrays; 128B-aligned k-slices

// ---------------- scratch (device globals; no runtime allocation) ----------
__device__ float g_h0s[B * 2 * H];            // [b][200] h0 at t=T-1
__device__ float g_xg1[(size_t)MTOT * G4];    // [t*B+b][n'] layer1-fwd gates (+bias), gate-interleaved
__device__ float g_h1f[B * H];
__device__ __nv_bfloat16 g_Ah[(size_t)MTOT * KPAD];   // h0 hi, [t*B+b][k]; cols 200..255 = 0
__device__ __nv_bfloat16 g_Al[(size_t)MTOT * KPAD];
__device__ __nv_bfloat16 g_Bh[400 * KPAD];            // W_ih_l1f rows gate-interleaved
__device__ __nv_bfloat16 g_Bl[400 * KPAD];

typedef unsigned long long u64;

__device__ __forceinline__ u64 pk2(float a, float b) {
    u64 r; asm("mov.b64 %0, {%1,%2};" : "=l"(r) : "f"(a), "f"(b)); return r;
}
__device__ __forceinline__ void upk2(u64 v, float& a, float& b) {
    asm("mov.b64 {%0,%1}, %2;" : "=f"(a), "=f"(b) : "l"(v));
}
__device__ __forceinline__ u64 ffma2(u64 a, u64 b, u64 c) {
    asm("fma.rn.f32x2 %0, %1, %2, %0;" : "+l"(c) : "l"(a), "l"(b)); return c;
}
// ---- activations via tanh.approx (1 MUFU each; sigma = 0.5*tanh(x/2)+0.5) --
__device__ __forceinline__ float ftanh_(float x) {
    float t; asm("tanh.approx.f32 %0, %1;" : "=f"(t) : "f"(x)); return t;
}
__device__ __forceinline__ float fsig(float x) {
    float t; asm("tanh.approx.f32 %0, %1;" : "=f"(t) : "f"(x * 0.5f));
    return fmaf(0.5f, t, 0.5f);
}
__device__ __forceinline__ uint32_t smem_u32(const void* p) {
    uint32_t a;
    asm("{ .reg .u64 t; cvta.to.shared.u64 t, %1; cvt.u32.u64 %0, t; }" : "=r"(a) : "l"(p));
    return a;
}

#define MMA_BF16(ac, a0,a1,a2,a3, b0,b1) \
    asm volatile("mma.sync.aligned.m16n8k16.row.col.f32.bf16.bf16.f32 " \
        "{%0,%1,%2,%3}, {%4,%5,%6,%7}, {%8,%9}, {%0,%1,%2,%3};" \
        : "+f"((ac)[0]), "+f"((ac)[1]), "+f"((ac)[2]), "+f"((ac)[3]) \
        : "r"(a0), "r"(a1), "r"(a2), "r"(a3), "r"(b0), "r"(b1))

#define CP_ASYNC16(dst, src) \
    asm volatile("cp.async.ca.shared.global [%0], [%1], 16;" :: "r"(dst), "l"(src))
#define CP_COMMIT() asm volatile("cp.async.commit_group;" ::: "memory")
#define CP_WAIT0()  asm volatile("cp.async.wait_group 0;" ::: "memory")

// ============================================================================
// TENSOR-CORE RECURRENCE (R12 config: 16 batches/CTA, 512 thr / 16 warps,
// 4 n-tile slots/warp, gate-interleaved n'=j*4+gate, ONE barrier/step;
// mode0 coalesced h copy to global). Activations now tanh.approx.
// ============================================================================
#define KSB     240
#define OFF_WL  96000
#define OFF_A   192000
#define ABUF    7680
#define RC_SMEM 207360
#define NTHR    512

__global__ void __launch_bounds__(NTHR, 1) lstm_rec_mma(
    const float* __restrict__ xg,
    const float* __restrict__ x,
    const float* __restrict__ whf, const float* __restrict__ whb,
    const float* __restrict__ wihf, const float* __restrict__ wihb,
    const float* __restrict__ bihf, const float* __restrict__ bhhf,
    const float* __restrict__ bihb, const float* __restrict__ bhhb,
    int mode)
{
    extern __shared__ char smc[];
    const uint32_t sb = smem_u32(smc);
    const int tid = threadIdx.x, wid = tid >> 5, lane = tid & 31;
    const int g = lane >> 2, t4 = lane & 3;
    const int dir = (mode == 0) ? (int)(blockIdx.x >> 6) : 0;
    const int b0  = (mode == 0) ? (int)(blockIdx.x & 63) * 16 : (int)blockIdx.x * 16;
    const float* wp  = dir ? whb  : whf;
    const float* wip = dir ? wihb : wihf;
    const float* bi_ = dir ? bihb : bihf;
    const float* bh_ = dir ? bhhb : bhhf;

    for (int i = tid; i < (RC_SMEM >> 4); i += NTHR)
        ((uint4*)smc)[i] = make_uint4(0, 0, 0, 0);
    __syncthreads();
    for (int i = tid; i < 400 * 100; i += NTHR) {
        int r = i / 100, k = i - r * 100;
        int np = (r % 100) * 4 + r / 100;
        float w = wp[i];
        __nv_bfloat16 hb = __float2bfloat16(w);
        __nv_bfloat16 lb = __float2bfloat16(w - __bfloat162float(hb));
        *(__nv_bfloat16*)(smc + np * KSB + k * 2) = hb;
        *(__nv_bfloat16*)(smc + OFF_WL + np * KSB + k * 2) = lb;
    }
    if (mode == 0) {
        for (int i = tid; i < 400 * INP; i += NTHR) {
            int r = i / INP, d = i - r * INP;
            int np = (r % 100) * 4 + r / 100;
            float w = wip[i];
            __nv_bfloat16 hb = __float2bfloat16(w);
            __nv_bfloat16 lb = __float2bfloat16(w - __bfloat162float(hb));
            *(__nv_bfloat16*)(smc + np * KSB + (100 + d) * 2) = hb;
            *(__nv_bfloat16*)(smc + OFF_WL + np * KSB + (100 + d) * 2) = lb;
        }
        if (tid < 16 * INP) {
            int bb = tid / INP, d = tid - (tid / INP) * INP;
            int tg0 = dir ? (T - 1) : 0;
            float xv = x[((size_t)(b0 + bb) * T + tg0) * INP + d];
            __nv_bfloat16 hb = __float2bfloat16(xv);
            __nv_bfloat16 lb = __float2bfloat16(xv - __bfloat162float(hb));
            *(__nv_bfloat16*)(smc + OFF_A + bb * KSB + (100 + d) * 2) = hb;
            *(__nv_bfloat16*)(smc + OFF_A + 3840 + bb * KSB + (100 + d) * 2) = lb;
        }
    }

    int  tl[4]; bool tv[4];
    float br[4][2];
    #pragma unroll
    for (int i = 0; i < 4; i++) {
        int t = wid + 16 * i;
        tv[i] = (t < 50); tl[i] = tv[i] ? t : 0;
        br[i][0] = br[i][1] = 0.f;
        if (mode == 0 && tv[i]) {
            int np = t * 8 + 2 * t4;
            int r0 = (np & 3) * 100 + (np >> 2);
            int r1 = ((np + 1) & 3) * 100 + ((np + 1) >> 2);
            br[i][0] = bi_[r0] + bh_[r0];
            br[i][1] = bi_[r1] + bh_[r1];
        }
    }
    float cst[4];
    #pragma unroll
    for (int i = 0; i < 4; i++) cst[i] = 0.f;

    float xp[4][4];
    if (mode == 1) {
        #pragma unroll
        for (int i = 0; i < 4; i++) {
            xp[i][0] = xp[i][1] = xp[i][2] = xp[i][3] = 0.f;
            if (tv[i]) {
                const float* p0 = xg + (size_t)(b0 + g) * 400 + tl[i] * 8 + 2 * t4;
                float2 v0 = *(const float2*)p0;
                float2 v1 = *(const float2*)(p0 + 3200);
                xp[i][0] = v0.x; xp[i][1] = v0.y; xp[i][2] = v1.x; xp[i][3] = v1.y;
            }
        }
    }
    __syncthreads();

    for (int ts = 0; ts < T; ts++) {
        const int cur = ts & 1, nxt = cur ^ 1;
        const int tg = dir ? (T - 1 - ts) : ts;

        float acc[4][4];
        if (mode == 0) {
            #pragma unroll
            for (int i = 0; i < 4; i++) {
                acc[i][0] = br[i][0]; acc[i][1] = br[i][1];
                acc[i][2] = br[i][0]; acc[i][3] = br[i][1];
            }
        } else {
            #pragma unroll
            for (int i = 0; i < 4; i++) {
                acc[i][0] = xp[i][0]; acc[i][1] = xp[i][1];
                acc[i][2] = xp[i][2]; acc[i][3] = xp[i][3];
            }
            if (ts + 1 < T) {
                #pragma unroll
                for (int i = 0; i < 4; i++) {
                    if (tv[i]) {
                        const float* p0 = xg + ((size_t)(ts + 1) * B + b0 + g) * 400 + tl[i] * 8 + 2 * t4;
                        float2 v0 = *(const float2*)p0;
                        float2 v1 = *(const float2*)(p0 + 3200);
                        xp[i][0] = v0.x; xp[i][1] = v0.y; xp[i][2] = v1.x; xp[i][3] = v1.y;
                    }
                }
            }
        }
        float xv = 0.f;
        if (mode == 0 && tid < 16 * INP && ts + 1 < T) {
            int bb = tid / INP, d = tid - (tid / INP) * INP;
            int tgn = dir ? (tg - 1) : (tg + 1);
            xv = x[((size_t)(b0 + bb) * T + tgn) * INP + d];
        }

        const uint32_t aBase = sb + OFF_A + cur * ABUF;
        #pragma unroll
        for (int kc = 0; kc < 7; kc++) {
            uint32_t ah[4], al[4];
            uint32_t aa = aBase + (lane & 15) * KSB + (lane >> 4) * 16 + kc * 32;
            asm volatile("ldmatrix.sync.aligned.m8n8.x4.shared.b16 {%0,%1,%2,%3}, [%4];"
                : "=r"(ah[0]), "=r"(ah[1]), "=r"(ah[2]), "=r"(ah[3]) : "r"(aa));
            asm volatile("ldmatrix.sync.aligned.m8n8.x4.shared.b16 {%0,%1,%2,%3}, [%4];"
                : "=r"(al[0]), "=r"(al[1]), "=r"(al[2]), "=r"(al[3]) : "r"(aa + 3840));

            uint32_t wh[4][2], wl[4][2];
            #pragma unroll
            for (int p = 0; p < 2; p++) {
                int m = lane >> 3;
                int tt = tl[2 * p + (m >> 1)];
                uint32_t wa = sb + (8 * tt + (lane & 7)) * KSB + (m & 1) * 16 + kc * 32;
                asm volatile("ldmatrix.sync.aligned.m8n8.x4.shared.b16 {%0,%1,%2,%3}, [%4];"
                    : "=r"(wh[2*p][0]), "=r"(wh[2*p][1]), "=r"(wh[2*p+1][0]), "=r"(wh[2*p+1][1])
                    : "r"(wa));
                asm volatile("ldmatrix.sync.aligned.m8n8.x4.shared.b16 {%0,%1,%2,%3}, [%4];"
                    : "=r"(wl[2*p][0]), "=r"(wl[2*p][1]), "=r"(wl[2*p+1][0]), "=r"(wl[2*p+1][1])
                    : "r"(wa + OFF_WL));
            }
            #pragma unroll
            for (int i = 0; i < 4; i++)
                MMA_BF16(acc[i], ah[0], ah[1], ah[2], ah[3], wh[i][0], wh[i][1]);
            #pragma unroll
            for (int i = 0; i < 4; i++)
                MMA_BF16(acc[i], al[0], al[1], al[2], al[3], wh[i][0], wh[i][1]);
            #pragma unroll
            for (int i = 0; i < 4; i++)
                MMA_BF16(acc[i], ah[0], ah[1], ah[2], ah[3], wl[i][0], wl[i][1]);
        }

        #pragma unroll
        for (int i = 0; i < 4; i++) {
            if (tv[i]) {
                float s0 = __shfl_xor_sync(0xffffffffu, acc[i][0], 1);
                float s1 = __shfl_xor_sync(0xffffffffu, acc[i][1], 1);
                float s2 = __shfl_xor_sync(0xffffffffu, acc[i][2], 1);
                float s3 = __shfl_xor_sync(0xffffffffu, acc[i][3], 1);
                bool odd = (t4 & 1);
                float gi = odd ? s2 : acc[i][0];
                float gf = odd ? s3 : acc[i][1];
                float gg = odd ? acc[i][2] : s0;
                float go = odd ? acc[i][3] : s1;
                float cv = fsig(gf) * cst[i] + fsig(gi) * ftanh_(gg);
                cst[i] = cv;
                float h = fsig(go) * ftanh_(cv);
                __nv_bfloat16 hh = __float2bfloat16(h);
                __nv_bfloat16 hl = __float2bfloat16(h - __bfloat162float(hh));
                int bu = g + (odd ? 8 : 0);
                int ju = 2 * tl[i] + (t4 >> 1);
                uint32_t off = OFF_A + nxt * ABUF + bu * KSB + ju * 2;
                *(__nv_bfloat16*)(smc + off) = hh;
                *(__nv_bfloat16*)(smc + off + 3840) = hl;
                if (mode == 0) {
                    if (tg == T - 1)
                        g_h0s[(size_t)(b0 + bu) * 200 + dir * 100 + ju] = h;
                } else if (ts == T - 1) {
                    g_h1f[(size_t)(b0 + bu) * 100 + ju] = h;
                }
            }
        }
        if (mode == 0 && tid < 16 * INP && ts + 1 < T) {
            int bb = tid / INP, d = tid - (tid / INP) * INP;
            __nv_bfloat16 hb = __float2bfloat16(xv);
            __nv_bfloat16 lb = __float2bfloat16(xv - __bfloat162float(hb));
            *(__nv_bfloat16*)(smc + OFF_A + nxt * ABUF + bb * KSB + (100 + d) * 2) = hb;
            *(__nv_bfloat16*)(smc + OFF_A + nxt * ABUF + 3840 + bb * KSB + (100 + d) * 2) = lb;
        }
        __syncthreads();

        if (mode == 0) {
            const char* st = smc + OFF_A + nxt * ABUF;
            for (int i = tid; i < 800; i += NTHR) {
                int arr = (i >= 400);
                int idx = i - arr * 400;
                int row = idx / 25, c8 = idx - row * 25;
                uint2 v = *(const uint2*)(st + arr * 3840 + row * KSB + c8 * 8);
                size_t gr = ((size_t)tg * B + b0 + row) * KPAD + dir * 100 + c8 * 4;
                *(uint2*)((arr ? g_Al : g_Ah) + gr) = v;
            }
        }
    }
}

// ============================================================================
// conv_b: W_ih_l1f -> bf16 hi/lo, rows gate-interleaved (n' = j*4+gate).
// ============================================================================
__global__ void conv_b_kernel(const float* __restrict__ wih)
{
    int i = blockIdx.x * 256 + threadIdx.x;
    if (i < 400 * 200) {
        int r = i / 200, k = i - r * 200;
        int np = (r % 100) * 4 + r / 100;
        float w = wih[i];
        __nv_bfloat16 hb = __float2bfloat16(w);
        __nv_bfloat16 lb = __float2bfloat16(w - __bfloat162float(hb));
        g_Bh[np * KPAD + k] = hb;
        g_Bl[np * KPAD + k] = lb;
    }
}

// ============================================================================
// xg1 GEMM: BM=128, BN=80, BK=64, 12 iters, cp.async double-buffered
// (no register staging -> 3 CTAs/SM). grid (5, 1024).
// ============================================================================
#define GRS   72
#define GA_B  (128 * GRS * 2)
#define GB_B  (80 * GRS * 2)
#define GOFF_B  (2 * GA_B)
#define GOFF_BI (2 * GA_B + 2 * GB_B)
#define GSMEM   (GOFF_BI + 1600)

__global__ void __launch_bounds__(256, 3) gemm_xg1_mma(
    const float* __restrict__ bih, const float* __restrict__ bhh)
{
    extern __shared__ char gsm[];
    const uint32_t sbase = smem_u32(gsm);
    float* bsm = (float*)(gsm + GOFF_BI);

    const int tid  = threadIdx.x;
    const int wid  = tid >> 5;
    const int lane = tid & 31;
    const int n0   = blockIdx.x * 80;
    const int m0   = blockIdx.y * 128;
    const int wm   = (wid >> 1) * 32;
    const int wn   = (wid & 1) * 40;

    for (int i = tid; i < 400; i += 256) {
        int r = (i & 3) * 100 + (i >> 2);
        bsm[i] = bih[r] + bhh[r];
    }

    float acc[2][5][4];
    #pragma unroll
    for (int mt = 0; mt < 2; mt++)
        #pragma unroll
        for (int nt = 0; nt < 5; nt++)
            #pragma unroll
            for (int e = 0; e < 4; e++) acc[mt][nt][e] = 0.f;

    const int arow = tid >> 1, ahalf = tid & 1;
    const int brow = tid >> 1, bhalf = tid & 1;
    const uint32_t adst0 = sbase + arow * (GRS * 2) + ahalf * 64;
    const uint32_t bdst0 = sbase + GOFF_B + brow * (GRS * 2) + bhalf * 64;

    // preload iter 0 (seg 0 = Ah*Bh, k-chunk 0) via cp.async
    {
        const char* ap = (const char*)(g_Ah + (size_t)(m0 + arow) * KPAD + ahalf * 32);
        #pragma unroll
        for (int i = 0; i < 4; i++) CP_ASYNC16(adst0 + i * 16, ap + i * 16);
        if (tid < 160) {
            const char* bp = (const char*)(g_Bh + (size_t)(n0 + brow) * KPAD + bhalf * 32);
            #pragma unroll
            for (int i = 0; i < 4; i++) CP_ASYNC16(bdst0 + i * 16, bp + i * 16);
        }
        CP_COMMIT(); CP_WAIT0();
    }
    __syncthreads();

    for (int it = 0; it < 12; it++) {
        const int cur = it & 1, nxt = cur ^ 1;
        if (it < 11) {
            const int it2 = it + 1;
            const int seg = it2 >> 2, kc = it2 & 3;
            const __nv_bfloat16* Ap = (seg == 1) ? g_Al : g_Ah;
            const __nv_bfloat16* Bp = (seg == 2) ? g_Bl : g_Bh;
            const char* ap = (const char*)(Ap + (size_t)(m0 + arow) * KPAD + kc * 64 + ahalf * 32);
            uint32_t ad = adst0 + nxt * GA_B;
            #pragma unroll
            for (int i = 0; i < 4; i++) CP_ASYNC16(ad + i * 16, ap + i * 16);
            if (tid < 160) {
                const char* bp = (const char*)(Bp + (size_t)(n0 + brow) * KPAD + kc * 64 + bhalf * 32);
                uint32_t bd = bdst0 + nxt * GB_B;
                #pragma unroll
                for (int i = 0; i < 4; i++) CP_ASYNC16(bd + i * 16, bp + i * 16);
            }
            CP_COMMIT();
        }

        const uint32_t abuf = sbase + cur * GA_B;
        const uint32_t bbuf = sbase + GOFF_B + cur * GB_B;
        #pragma unroll
        for (int kk = 0; kk < 4; kk++) {
            uint32_t af[2][4];
            #pragma unroll
            for (int mt = 0; mt < 2; mt++) {
                uint32_t addr = abuf + (wm + mt * 16 + (lane & 15)) * (GRS * 2)
                              + (lane >> 4) * 16 + kk * 32;
                asm volatile("ldmatrix.sync.aligned.m8n8.x4.shared.b16 {%0,%1,%2,%3}, [%4];"
                    : "=r"(af[mt][0]), "=r"(af[mt][1]), "=r"(af[mt][2]), "=r"(af[mt][3])
                    : "r"(addr));
            }
            uint32_t bf[5][2];
            #pragma unroll
            for (int nt = 0; nt < 5; nt++) {
                uint32_t addr = bbuf + (wn + nt * 8 + (lane & 7)) * (GRS * 2)
                              + ((lane >> 3) & 1) * 16 + kk * 32;
                asm volatile("ldmatrix.sync.aligned.m8n8.x2.shared.b16 {%0,%1}, [%2];"
                    : "=r"(bf[nt][0]), "=r"(bf[nt][1]) : "r"(addr));
            }
            #pragma unroll
            for (int mt = 0; mt < 2; mt++)
                #pragma unroll
                for (int nt = 0; nt < 5; nt++)
                    MMA_BF16(acc[mt][nt], af[mt][0], af[mt][1], af[mt][2], af[mt][3],
                             bf[nt][0], bf[nt][1]);
        }

        if (it < 11) CP_WAIT0();
        __syncthreads();
    }

    const int gid = lane >> 2, t4 = lane & 3;
    #pragma unroll
    for (int mt = 0; mt < 2; mt++) {
        #pragma unroll
        for (int nt = 0; nt < 5; nt++) {
            int mrow = m0 + wm + mt * 16 + gid;
            int ncol = n0 + wn + nt * 8 + t4 * 2;
            float by = bsm[ncol + 1];
            float2 v0 = make_float2(acc[mt][nt][0] + bsm[ncol], acc[mt][nt][1] + by);
            float2 v1 = make_float2(acc[mt][nt][2] + bsm[ncol], acc[mt][nt][3] + by);
            *(float2*)&g_xg1[(size_t)mrow * 400 + ncol]       = v0;
            *(float2*)&g_xg1[(size_t)(mrow + 8) * 400 + ncol] = v1;
        }
    }
}

// ============================================================================
// lstm_final: layer1 backward single step (c0=0) + FC + softmax.
// grid 128 (8 batches/CTA) to fill the chip.
// ============================================================================
#define FN_SMEMF (30000 + 200*10 + 800 + 300 + 600 + 4 + 24)

__global__ void __launch_bounds__(256, 1) lstm_final(
    const float* __restrict__ wih1b,
    const float* __restrict__ bih1b, const float* __restrict__ bhh1b,
    const float* __restrict__ fc_w,  const float* __restrict__ fc_b,
    float* __restrict__ out)
{
    extern __shared__ float sm[];
    float* wT   = sm;                    // [100 k][300]
    float* h0s  = sm + 30000;            // [200 k][10] (8 batches + pad 2)
    float* h1bs = sm + 32000;            // [8][100]
    float* b3   = sm + 32800;            // [300]
    float* fcw  = sm + 33100;            // [600]
    float* fcb  = sm + 33700;            // [4]
    float* lg   = sm + 33704;            // [24]

    const int tid = threadIdx.x;
    const int b0 = blockIdx.x * 8;

    for (int i = tid; i < 8 * 200; i += 256) {
        int b = i / 200, k = i - b * 200;
        h0s[k * 10 + b] = g_h0s[(size_t)(b0 + b) * 200 + k];
    }
    for (int i = tid; i < 300; i += 256) {
        int g3 = i / 100, j = i - g3 * 100;
        int row = j + (g3 == 0 ? 0 : (g3 == 1 ? 200 : 300));
        b3[i] = bih1b[row] + bhh1b[row];
    }
    for (int i = tid; i < 600; i += 256) fcw[i] = fc_w[i];
    if (tid < 3) fcb[tid] = fc_b[tid];

    const int  jj  = tid & 127;
    const int  grp = tid >> 7;
    const bool act = (jj < H);

    u64 acc[2][3];
    #pragma unroll
    for (int p = 0; p < 2; p++)
        #pragma unroll
        for (int g = 0; g < 3; g++) acc[p][g] = pk2(0.f, 0.f);

    for (int kt = 0; kt < 2; kt++) {
        __syncthreads();
        for (int i = tid; i < 30000; i += 256) {
            int k = i % 100, j100 = i / 100;
            int grow = j100 + (j100 >= 100 ? 100 : 0);
            wT[k * 300 + j100] = wih1b[(size_t)grow * 200 + kt * 100 + k];
        }
        __syncthreads();
        if (act) {
            #pragma unroll 2
            for (int k = 0; k < 100; k++) {
                const float* wr = wT + k * 300 + jj;
                u64 w0 = pk2(wr[0], wr[0]);
                u64 w1 = pk2(wr[100], wr[100]);
                u64 w2 = pk2(wr[200], wr[200]);
                const float* hb = h0s + (kt * 100 + k) * 10 + grp * 4;
                #pragma unroll
                for (int p = 0; p < 2; p++) {
                    u64 hv = *(const u64*)(hb + 2 * p);
                    acc[p][0] = ffma2(w0, hv, acc[p][0]);
                    acc[p][1] = ffma2(w1, hv, acc[p][1]);
                    acc[p][2] = ffma2(w2, hv, acc[p][2]);
                }
            }
        }
    }
    if (act) {
        #pragma unroll
        for (int p = 0; p < 2; p++) {
            float i0, i1, g0, g1, o0, o1;
            upk2(acc[p][0], i0, i1);
            upk2(acc[p][1], g0, g1);
            upk2(acc[p][2], o0, o1);
            float bi = b3[jj], bg = b3[100 + jj], bo = b3[200 + jj];
            i0 += bi; i1 += bi; g0 += bg; g1 += bg; o0 += bo; o1 += bo;
            float c0 = fsig(i0) * ftanh_(g0);
            float c1 = fsig(i1) * ftanh_(g1);
            int bl = grp * 4 + 2 * p;
            h1bs[bl * 100 + jj]       = fsig(o0) * ftanh_(c0);
            h1bs[(bl + 1) * 100 + jj] = fsig(o1) * ftanh_(c1);
        }
    }
    __syncthreads();
    if (tid < 24) {
        int b = tid / 3, cls = tid - b * 3;
        float a = fcb[cls];
        const float* h1f = g_h1f + (size_t)(b0 + b) * 100;
        #pragma unroll 4
        for (int j = 0; j < 100; j++) {
            a += h1f[j]            * fcw[cls * 200 + j];
            a += h1bs[b * 100 + j] * fcw[cls * 200 + 100 + j];
        }
        lg[tid] = a;
    }
    __syncthreads();
    if (tid < 8) {
        int b = tid;
        float l0 = lg[b * 3], l1 = lg[b * 3 + 1], l2 = lg[b * 3 + 2];
        float m = fmaxf(l0, fmaxf(l1, l2));
        float e0 = __expf(l0 - m), e1 = __expf(l1 - m), e2 = __expf(l2 - m);
        float s = 1.0f / (e0 + e1 + e2);
        out[(b0 + b) * 3 + 0] = e0 * s;
        out[(b0 + b) * 3 + 1] = e1 * s;
        out[(b0 + b) * 3 + 2] = e2 * s;
    }
}

// ============================================================================
extern "C" void kernel_launch(void* const* d_in, const int* in_sizes, int n_in,
                              void* d_out, int out_size)
{
    (void)in_sizes; (void)n_in; (void)out_size;
    const float* x     = (const float*)d_in[0];
    const float* wih0f = (const float*)d_in[1];
    const float* whh0f = (const float*)d_in[2];
    const float* bih0f = (const float*)d_in[3];
    const float* bhh0f = (const float*)d_in[4];
    const float* wih0b = (const float*)d_in[5];
    const float* whh0b = (const float*)d_in[6];
    const float* bih0b = (const float*)d_in[7];
    const float* bhh0b = (const float*)d_in[8];
    const float* wih1f = (const float*)d_in[9];
    const float* whh1f = (const float*)d_in[10];
    const float* bih1f = (const float*)d_in[11];
    const float* bhh1f = (const float*)d_in[12];
    const float* wih1b = (const float*)d_in[13];
    const float* bih1b = (const float*)d_in[15];
    const float* bhh1b = (const float*)d_in[16];
    const float* fcw   = (const float*)d_in[17];
    const float* fcb   = (const float*)d_in[18];
    float* out = (float*)d_out;

    float* xg1p; cudaGetSymbolAddress((void**)&xg1p, g_xg1);

    cudaFuncSetAttribute(lstm_rec_mma,  cudaFuncAttributeMaxDynamicSharedMemorySize, RC_SMEM);
    cudaFuncSetAttribute(gemm_xg1_mma,  cudaFuncAttributeMaxDynamicSharedMemorySize, GSMEM);
    cudaFuncSetAttribute(lstm_final,    cudaFuncAttributeMaxDynamicSharedMemorySize, FN_SMEMF * 4);

    conv_b_kernel<<<(400 * 200 + 255) / 256, 256>>>(wih1f);
    lstm_rec_mma<<<128, NTHR, RC_SMEM>>>(nullptr, x, whh0f, whh0b, wih0f, wih0b,
                                         bih0f, bhh0f, bih0b, bhh0b, 0);
    gemm_xg1_mma<<<dim3(5, 1024), 256, GSMEM>>>(bih1f, bhh1f);
    lstm_rec_mma<<<64, NTHR, RC_SMEM>>>(xg1p, nullptr, whh1f, whh1f, wih1f, wih1f,
                                        bih1f, bhh1f, bih1f, bhh1f, 1);
    lstm_final<<<128, 256, FN_SMEMF * 4>>>(wih1b, bih1b, bhh1b, fcw, fcb, out);
}

// round 14
// speedup vs baseline: 1.6705x; 1.0558x over previous
#include <cuda_runtime.h>
#include <cuda_bf16.h>
#include <cstdint>

#define B 1024
#define T 128
#define INP 5
#define H 100
#define G4 400
#define MTOT (B*T)
#define KPAD 256          // k-stride of bf16 A/B arrays; 128B-aligned k-slices

// ---------------- scratch (device globals; no runtime allocation) ----------
__device__ float g_h0s[B * 2 * H];            // [b][200] h0 at t=T-1
// xg1 TILE layout: [(t*64+bg)*50 + tile][128]  (bg = batch-group of 16,
// tile = n'/8; inner order [g(8)][t4(4)][e(2)][hi(2)] -> one float4/lane)
__device__ float g_xg1[(size_t)MTOT * G4];
__device__ float g_h1f[B * H];
__device__ __nv_bfloat16 g_Ah[(size_t)MTOT * KPAD];   // h0 hi, [t*B+b][k]; cols 200..255 = 0
__device__ __nv_bfloat16 g_Al[(size_t)MTOT * KPAD];
__device__ __nv_bfloat16 g_Bh[400 * KPAD];            // W_ih_l1f rows gate-interleaved
__device__ __nv_bfloat16 g_Bl[400 * KPAD];

typedef unsigned long long u64;

__device__ __forceinline__ u64 pk2(float a, float b) {
    u64 r; asm("mov.b64 %0, {%1,%2};" : "=l"(r) : "f"(a), "f"(b)); return r;
}
__device__ __forceinline__ void upk2(u64 v, float& a, float& b) {
    asm("mov.b64 {%0,%1}, %2;" : "=f"(a), "=f"(b) : "l"(v));
}
__device__ __forceinline__ u64 ffma2(u64 a, u64 b, u64 c) {
    asm("fma.rn.f32x2 %0, %1, %2, %0;" : "+l"(c) : "l"(a), "l"(b)); return c;
}
// ---- activations via tanh.approx (1 MUFU each; sigma = 0.5*tanh(x/2)+0.5) --
__device__ __forceinline__ float ftanh_(float x) {
    float t; asm("tanh.approx.f32 %0, %1;" : "=f"(t) : "f"(x)); return t;
}
__device__ __forceinline__ float fsig(float x) {
    float t; asm("tanh.approx.f32 %0, %1;" : "=f"(t) : "f"(x * 0.5f));
    return fmaf(0.5f, t, 0.5f);
}
__device__ __forceinline__ uint32_t smem_u32(const void* p) {
    uint32_t a;
    asm("{ .reg .u64 t; cvta.to.shared.u64 t, %1; cvt.u32.u64 %0, t; }" : "=r"(a) : "l"(p));
    return a;
}

#define MMA_BF16(ac, a0,a1,a2,a3, b0,b1) \
    asm volatile("mma.sync.aligned.m16n8k16.row.col.f32.bf16.bf16.f32 " \
        "{%0,%1,%2,%3}, {%4,%5,%6,%7}, {%8,%9}, {%0,%1,%2,%3};" \
        : "+f"((ac)[0]), "+f"((ac)[1]), "+f"((ac)[2]), "+f"((ac)[3]) \
        : "r"(a0), "r"(a1), "r"(a2), "r"(a3), "r"(b0), "r"(b1))

#define CP_ASYNC16(dst, src) \
    asm volatile("cp.async.ca.shared.global [%0], [%1], 16;" :: "r"(dst), "l"(src))
#define CP_COMMIT() asm volatile("cp.async.commit_group;" ::: "memory")
#define CP_WAIT0()  asm volatile("cp.async.wait_group 0;" ::: "memory")

// ============================================================================
// TENSOR-CORE RECURRENCE (16 batches/CTA, 512 thr / 16 warps, 4 n-tile
// slots/warp, gate-interleaved n'=j*4+gate, ONE barrier/step; mode0 coalesced
// h copy to global). mode1 xg loads now ONE coalesced LDG.128 per slot.
// ============================================================================
#define KSB     240
#define OFF_WL  96000
#define OFF_A   192000
#define ABUF    7680
#define RC_SMEM 207360
#define NTHR    512

__global__ void __launch_bounds__(NTHR, 1) lstm_rec_mma(
    const float* __restrict__ xg,
    const float* __restrict__ x,
    const float* __restrict__ whf, const float* __restrict__ whb,
    const float* __restrict__ wihf, const float* __restrict__ wihb,
    const float* __restrict__ bihf, const float* __restrict__ bhhf,
    const float* __restrict__ bihb, const float* __restrict__ bhhb,
    int mode)
{
    extern __shared__ char smc[];
    const uint32_t sb = smem_u32(smc);
    const int tid = threadIdx.x, wid = tid >> 5, lane = tid & 31;
    const int g = lane >> 2, t4 = lane & 3;
    const int dir = (mode == 0) ? (int)(blockIdx.x >> 6) : 0;
    const int b0  = (mode == 0) ? (int)(blockIdx.x & 63) * 16 : (int)blockIdx.x * 16;
    const int bg  = b0 >> 4;
    const float* wp  = dir ? whb  : whf;
    const float* wip = dir ? wihb : wihf;
    const float* bi_ = dir ? bihb : bihf;
    const float* bh_ = dir ? bhhb : bhhf;

    for (int i = tid; i < (RC_SMEM >> 4); i += NTHR)
        ((uint4*)smc)[i] = make_uint4(0, 0, 0, 0);
    __syncthreads();
    for (int i = tid; i < 400 * 100; i += NTHR) {
        int r = i / 100, k = i - r * 100;
        int np = (r % 100) * 4 + r / 100;
        float w = wp[i];
        __nv_bfloat16 hb = __float2bfloat16(w);
        __nv_bfloat16 lb = __float2bfloat16(w - __bfloat162float(hb));
        *(__nv_bfloat16*)(smc + np * KSB + k * 2) = hb;
        *(__nv_bfloat16*)(smc + OFF_WL + np * KSB + k * 2) = lb;
    }
    if (mode == 0) {
        for (int i = tid; i < 400 * INP; i += NTHR) {
            int r = i / INP, d = i - r * INP;
            int np = (r % 100) * 4 + r / 100;
            float w = wip[i];
            __nv_bfloat16 hb = __float2bfloat16(w);
            __nv_bfloat16 lb = __float2bfloat16(w - __bfloat162float(hb));
            *(__nv_bfloat16*)(smc + np * KSB + (100 + d) * 2) = hb;
            *(__nv_bfloat16*)(smc + OFF_WL + np * KSB + (100 + d) * 2) = lb;
        }
        if (tid < 16 * INP) {
            int bb = tid / INP, d = tid - (tid / INP) * INP;
            int tg0 = dir ? (T - 1) : 0;
            float xv = x[((size_t)(b0 + bb) * T + tg0) * INP + d];
            __nv_bfloat16 hb = __float2bfloat16(xv);
            __nv_bfloat16 lb = __float2bfloat16(xv - __bfloat162float(hb));
            *(__nv_bfloat16*)(smc + OFF_A + bb * KSB + (100 + d) * 2) = hb;
            *(__nv_bfloat16*)(smc + OFF_A + 3840 + bb * KSB + (100 + d) * 2) = lb;
        }
    }

    int  tl[4]; bool tv[4];
    float br[4][2];
    #pragma unroll
    for (int i = 0; i < 4; i++) {
        int t = wid + 16 * i;
        tv[i] = (t < 50); tl[i] = tv[i] ? t : 0;
        br[i][0] = br[i][1] = 0.f;
        if (mode == 0 && tv[i]) {
            int np = t * 8 + 2 * t4;
            int r0 = (np & 3) * 100 + (np >> 2);
            int r1 = ((np + 1) & 3) * 100 + ((np + 1) >> 2);
            br[i][0] = bi_[r0] + bh_[r0];
            br[i][1] = bi_[r1] + bh_[r1];
        }
    }
    float cst[4];
    #pragma unroll
    for (int i = 0; i < 4; i++) cst[i] = 0.f;

    // mode1: coalesced tile loads; lane reads float4 {c0, c2, c1, c3}
    float4 xp[4];
    if (mode == 1) {
        #pragma unroll
        for (int i = 0; i < 4; i++) {
            xp[i] = make_float4(0.f, 0.f, 0.f, 0.f);
            if (tv[i])
                xp[i] = *(const float4*)(xg + ((size_t)(0 * 64 + bg) * 50 + tl[i]) * 128 + lane * 4);
        }
    }
    __syncthreads();

    for (int ts = 0; ts < T; ts++) {
        const int cur = ts & 1, nxt = cur ^ 1;
        const int tg = dir ? (T - 1 - ts) : ts;

        float acc[4][4];
        if (mode == 0) {
            #pragma unroll
            for (int i = 0; i < 4; i++) {
                acc[i][0] = br[i][0]; acc[i][1] = br[i][1];
                acc[i][2] = br[i][0]; acc[i][3] = br[i][1];
            }
        } else {
            #pragma unroll
            for (int i = 0; i < 4; i++) {
                acc[i][0] = xp[i].x; acc[i][1] = xp[i].z;   // c0, c1
                acc[i][2] = xp[i].y; acc[i][3] = xp[i].w;   // c2, c3
            }
            if (ts + 1 < T) {
                #pragma unroll
                for (int i = 0; i < 4; i++)
                    if (tv[i])
                        xp[i] = *(const float4*)(xg + (((size_t)(ts + 1) * 64 + bg) * 50 + tl[i]) * 128 + lane * 4);
            }
        }
        float xv = 0.f;
        if (mode == 0 && tid < 16 * INP && ts + 1 < T) {
            int bb = tid / INP, d = tid - (tid / INP) * INP;
            int tgn = dir ? (tg - 1) : (tg + 1);
            xv = x[((size_t)(b0 + bb) * T + tgn) * INP + d];
        }

        const uint32_t aBase = sb + OFF_A + cur * ABUF;
        #pragma unroll
        for (int kc = 0; kc < 7; kc++) {
            uint32_t ah[4], al[4];
            uint32_t aa = aBase + (lane & 15) * KSB + (lane >> 4) * 16 + kc * 32;
            asm volatile("ldmatrix.sync.aligned.m8n8.x4.shared.b16 {%0,%1,%2,%3}, [%4];"
                : "=r"(ah[0]), "=r"(ah[1]), "=r"(ah[2]), "=r"(ah[3]) : "r"(aa));
            asm volatile("ldmatrix.sync.aligned.m8n8.x4.shared.b16 {%0,%1,%2,%3}, [%4];"
                : "=r"(al[0]), "=r"(al[1]), "=r"(al[2]), "=r"(al[3]) : "r"(aa + 3840));

            uint32_t wh[4][2], wl[4][2];
            #pragma unroll
            for (int p = 0; p < 2; p++) {
                int m = lane >> 3;
                int tt = tl[2 * p + (m >> 1)];
                uint32_t wa = sb + (8 * tt + (lane & 7)) * KSB + (m & 1) * 16 + kc * 32;
                asm volatile("ldmatrix.sync.aligned.m8n8.x4.shared.b16 {%0,%1,%2,%3}, [%4];"
                    : "=r"(wh[2*p][0]), "=r"(wh[2*p][1]), "=r"(wh[2*p+1][0]), "=r"(wh[2*p+1][1])
                    : "r"(wa));
                asm volatile("ldmatrix.sync.aligned.m8n8.x4.shared.b16 {%0,%1,%2,%3}, [%4];"
                    : "=r"(wl[2*p][0]), "=r"(wl[2*p][1]), "=r"(wl[2*p+1][0]), "=r"(wl[2*p+1][1])
                    : "r"(wa + OFF_WL));
            }
            #pragma unroll
            for (int i = 0; i < 4; i++)
                MMA_BF16(acc[i], ah[0], ah[1], ah[2], ah[3], wh[i][0], wh[i][1]);
            #pragma unroll
            for (int i = 0; i < 4; i++)
                MMA_BF16(acc[i], al[0], al[1], al[2], al[3], wh[i][0], wh[i][1]);
            #pragma unroll
            for (int i = 0; i < 4; i++)
                MMA_BF16(acc[i], ah[0], ah[1], ah[2], ah[3], wl[i][0], wl[i][1]);
        }

        #pragma unroll
        for (int i = 0; i < 4; i++) {
            if (tv[i]) {
                float s0 = __shfl_xor_sync(0xffffffffu, acc[i][0], 1);
                float s1 = __shfl_xor_sync(0xffffffffu, acc[i][1], 1);
                float s2 = __shfl_xor_sync(0xffffffffu, acc[i][2], 1);
                float s3 = __shfl_xor_sync(0xffffffffu, acc[i][3], 1);
                bool odd = (t4 & 1);
                float gi = odd ? s2 : acc[i][0];
                float gf = odd ? s3 : acc[i][1];
                float gg = odd ? acc[i][2] : s0;
                float go = odd ? acc[i][3] : s1;
                float cv = fsig(gf) * cst[i] + fsig(gi) * ftanh_(gg);
                cst[i] = cv;
                float h = fsig(go) * ftanh_(cv);
                __nv_bfloat16 hh = __float2bfloat16(h);
                __nv_bfloat16 hl = __float2bfloat16(h - __bfloat162float(hh));
                int bu = g + (odd ? 8 : 0);
                int ju = 2 * tl[i] + (t4 >> 1);
                uint32_t off = OFF_A + nxt * ABUF + bu * KSB + ju * 2;
                *(__nv_bfloat16*)(smc + off) = hh;
                *(__nv_bfloat16*)(smc + off + 3840) = hl;
                if (mode == 0) {
                    if (tg == T - 1)
                        g_h0s[(size_t)(b0 + bu) * 200 + dir * 100 + ju] = h;
                } else if (ts == T - 1) {
                    g_h1f[(size_t)(b0 + bu) * 100 + ju] = h;
                }
            }
        }
        if (mode == 0 && tid < 16 * INP && ts + 1 < T) {
            int bb = tid / INP, d = tid - (tid / INP) * INP;
            __nv_bfloat16 hb = __float2bfloat16(xv);
            __nv_bfloat16 lb = __float2bfloat16(xv - __bfloat162float(hb));
            *(__nv_bfloat16*)(smc + OFF_A + nxt * ABUF + bb * KSB + (100 + d) * 2) = hb;
            *(__nv_bfloat16*)(smc + OFF_A + nxt * ABUF + 3840 + bb * KSB + (100 + d) * 2) = lb;
        }
        __syncthreads();

        if (mode == 0) {
            const char* st = smc + OFF_A + nxt * ABUF;
            for (int i = tid; i < 800; i += NTHR) {
                int arr = (i >= 400);
                int idx = i - arr * 400;
                int row = idx / 25, c8 = idx - row * 25;
                uint2 v = *(const uint2*)(st + arr * 3840 + row * KSB + c8 * 8);
                size_t gr = ((size_t)tg * B + b0 + row) * KPAD + dir * 100 + c8 * 4;
                *(uint2*)((arr ? g_Al : g_Ah) + gr) = v;
            }
        }
    }
}

// ============================================================================
// conv_b: W_ih_l1f -> bf16 hi/lo, rows gate-interleaved (n' = j*4+gate).
// ============================================================================
__global__ void conv_b_kernel(const float* __restrict__ wih)
{
    int i = blockIdx.x * 256 + threadIdx.x;
    if (i < 400 * 200) {
        int r = i / 200, k = i - r * 200;
        int np = (r % 100) * 4 + r / 100;
        float w = wih[i];
        __nv_bfloat16 hb = __float2bfloat16(w);
        __nv_bfloat16 lb = __float2bfloat16(w - __bfloat162float(hb));
        g_Bh[np * KPAD + k] = hb;
        g_Bl[np * KPAD + k] = lb;
    }
}

// ============================================================================
// xg1 GEMM: BM=128, BN=80, BK=64, 12 iters, cp.async double-buffered.
// Epilogue writes the TILE layout: one dense float4 per (mt,nt) per thread.
// grid (5, 1024).
// ============================================================================
#define GRS   72
#define GA_B  (128 * GRS * 2)
#define GB_B  (80 * GRS * 2)
#define GOFF_B  (2 * GA_B)
#define GOFF_BI (2 * GA_B + 2 * GB_B)
#define GSMEM   (GOFF_BI + 1600)

__global__ void __launch_bounds__(256, 3) gemm_xg1_mma(
    const float* __restrict__ bih, const float* __restrict__ bhh)
{
    extern __shared__ char gsm[];
    const uint32_t sbase = smem_u32(gsm);
    float* bsm = (float*)(gsm + GOFF_BI);

    const int tid  = threadIdx.x;
    const int wid  = tid >> 5;
    const int lane = tid & 31;
    const int n0   = blockIdx.x * 80;
    const int m0   = blockIdx.y * 128;
    const int wm   = (wid >> 1) * 32;
    const int wn   = (wid & 1) * 40;

    for (int i = tid; i < 400; i += 256) {
        int r = (i & 3) * 100 + (i >> 2);
        bsm[i] = bih[r] + bhh[r];
    }

    float acc[2][5][4];
    #pragma unroll
    for (int mt = 0; mt < 2; mt++)
        #pragma unroll
        for (int nt = 0; nt < 5; nt++)
            #pragma unroll
            for (int e = 0; e < 4; e++) acc[mt][nt][e] = 0.f;

    const int arow = tid >> 1, ahalf = tid & 1;
    const int brow = tid >> 1, bhalf = tid & 1;
    const uint32_t adst0 = sbase + arow * (GRS * 2) + ahalf * 64;
    const uint32_t bdst0 = sbase + GOFF_B + brow * (GRS * 2) + bhalf * 64;

    {
        const char* ap = (const char*)(g_Ah + (size_t)(m0 + arow) * KPAD + ahalf * 32);
        #pragma unroll
        for (int i = 0; i < 4; i++) CP_ASYNC16(adst0 + i * 16, ap + i * 16);
        if (tid < 160) {
            const char* bp = (const char*)(g_Bh + (size_t)(n0 + brow) * KPAD + bhalf * 32);
            #pragma unroll
            for (int i = 0; i < 4; i++) CP_ASYNC16(bdst0 + i * 16, bp + i * 16);
        }
        CP_COMMIT(); CP_WAIT0();
    }
    __syncthreads();

    for (int it = 0; it < 12; it++) {
        const int cur = it & 1, nxt = cur ^ 1;
        if (it < 11) {
            const int it2 = it + 1;
            const int seg = it2 >> 2, kc = it2 & 3;
            const __nv_bfloat16* Ap = (seg == 1) ? g_Al : g_Ah;
            const __nv_bfloat16* Bp = (seg == 2) ? g_Bl : g_Bh;
            const char* ap = (const char*)(Ap + (size_t)(m0 + arow) * KPAD + kc * 64 + ahalf * 32);
            uint32_t ad = adst0 + nxt * GA_B;
            #pragma unroll
            for (int i = 0; i < 4; i++) CP_ASYNC16(ad + i * 16, ap + i * 16);
            if (tid < 160) {
                const char* bp = (const char*)(Bp + (size_t)(n0 + brow) * KPAD + kc * 64 + bhalf * 32);
                uint32_t bd = bdst0 + nxt * GB_B;
                #pragma unroll
                for (int i = 0; i < 4; i++) CP_ASYNC16(bd + i * 16, bp + i * 16);
            }
            CP_COMMIT();
        }

        const uint32_t abuf = sbase + cur * GA_B;
        const uint32_t bbuf = sbase + GOFF_B + cur * GB_B;
        #pragma unroll
        for (int kk = 0; kk < 4; kk++) {
            uint32_t af[2][4];
            #pragma unroll
            for (int mt = 0; mt < 2; mt++) {
                uint32_t addr = abuf + (wm + mt * 16 + (lane & 15)) * (GRS * 2)
                              + (lane >> 4) * 16 + kk * 32;
                asm volatile("ldmatrix.sync.aligned.m8n8.x4.shared.b16 {%0,%1,%2,%3}, [%4];"
                    : "=r"(af[mt][0]), "=r"(af[mt][1]), "=r"(af[mt][2]), "=r"(af[mt][3])
                    : "r"(addr));
            }
            uint32_t bf[5][2];
            #pragma unroll
            for (int nt = 0; nt < 5; nt++) {
                uint32_t addr = bbuf + (wn + nt * 8 + (lane & 7)) * (GRS * 2)
                              + ((lane >> 3) & 1) * 16 + kk * 32;
                asm volatile("ldmatrix.sync.aligned.m8n8.x2.shared.b16 {%0,%1}, [%2];"
                    : "=r"(bf[nt][0]), "=r"(bf[nt][1]) : "r"(addr));
            }
            #pragma unroll
            for (int mt = 0; mt < 2; mt++)
                #pragma unroll
                for (int nt = 0; nt < 5; nt++)
                    MMA_BF16(acc[mt][nt], af[mt][0], af[mt][1], af[mt][2], af[mt][3],
                             bf[nt][0], bf[nt][1]);
        }

        if (it < 11) CP_WAIT0();
        __syncthreads();
    }

    // epilogue -> TILE layout: float4 {c0+b0, c2+b0, c1+b1, c3+b1} per (mt,nt)
    const int gid = lane >> 2, t4 = lane & 3;
    const int tq = m0 >> 10;                   // t index (constant per CTA)
    #pragma unroll
    for (int mt = 0; mt < 2; mt++) {
        int bgq = (((m0 & 1023) + wm + mt * 16) >> 4);
        #pragma unroll
        for (int nt = 0; nt < 5; nt++) {
            int ncol = n0 + wn + nt * 8 + t4 * 2;
            int tile = (n0 + wn) / 8 + nt;
            float b0v = bsm[ncol], b1v = bsm[ncol + 1];
            float4 v = make_float4(acc[mt][nt][0] + b0v, acc[mt][nt][2] + b0v,
                                   acc[mt][nt][1] + b1v, acc[mt][nt][3] + b1v);
            *(float4*)(g_xg1 + (((size_t)tq * 64 + bgq) * 50 + tile) * 128
                       + (gid * 4 + t4) * 4) = v;
        }
    }
}

// ============================================================================
// lstm_final: layer1 backward single step (c0=0) + FC + softmax. grid 128.
// ============================================================================
#define FN_SMEMF (30000 + 200*10 + 800 + 300 + 600 + 4 + 24)

__global__ void __launch_bounds__(256, 1) lstm_final(
    const float* __restrict__ wih1b,
    const float* __restrict__ bih1b, const float* __restrict__ bhh1b,
    const float* __restrict__ fc_w,  const float* __restrict__ fc_b,
    float* __restrict__ out)
{
    extern __shared__ float sm[];
    float* wT   = sm;                    // [100 k][300]
    float* h0s  = sm + 30000;            // [200 k][10]
    float* h1bs = sm + 32000;            // [8][100]
    float* b3   = sm + 32800;            // [300]
    float* fcw  = sm + 33100;            // [600]
    float* fcb  = sm + 33700;            // [4]
    float* lg   = sm + 33704;            // [24]

    const int tid = threadIdx.x;
    const int b0 = blockIdx.x * 8;

    for (int i = tid; i < 8 * 200; i += 256) {
        int b = i / 200, k = i - b * 200;
        h0s[k * 10 + b] = g_h0s[(size_t)(b0 + b) * 200 + k];
    }
    for (int i = tid; i < 300; i += 256) {
        int g3 = i / 100, j = i - g3 * 100;
        int row = j + (g3 == 0 ? 0 : (g3 == 1 ? 200 : 300));
        b3[i] = bih1b[row] + bhh1b[row];
    }
    for (int i = tid; i < 600; i += 256) fcw[i] = fc_w[i];
    if (tid < 3) fcb[tid] = fc_b[tid];

    const int  jj  = tid & 127;
    const int  grp = tid >> 7;
    const bool act = (jj < H);

    u64 acc[2][3];
    #pragma unroll
    for (int p = 0; p < 2; p++)
        #pragma unroll
        for (int g = 0; g < 3; g++) acc[p][g] = pk2(0.f, 0.f);

    for (int kt = 0; kt < 2; kt++) {
        __syncthreads();
        for (int i = tid; i < 30000; i += 256) {
            int k = i % 100, j100 = i / 100;
            int grow = j100 + (j100 >= 100 ? 100 : 0);
            wT[k * 300 + j100] = wih1b[(size_t)grow * 200 + kt * 100 + k];
        }
        __syncthreads();
        if (act) {
            #pragma unroll 2
            for (int k = 0; k < 100; k++) {
                const float* wr = wT + k * 300 + jj;
                u64 w0 = pk2(wr[0], wr[0]);
                u64 w1 = pk2(wr[100], wr[100]);
                u64 w2 = pk2(wr[200], wr[200]);
                const float* hb = h0s + (kt * 100 + k) * 10 + grp * 4;
                #pragma unroll
                for (int p = 0; p < 2; p++) {
                    u64 hv = *(const u64*)(hb + 2 * p);
                    acc[p][0] = ffma2(w0, hv, acc[p][0]);
                    acc[p][1] = ffma2(w1, hv, acc[p][1]);
                    acc[p][2] = ffma2(w2, hv, acc[p][2]);
                }
            }
        }
    }
    if (act) {
        #pragma unroll
        for (int p = 0; p < 2; p++) {
            float i0, i1, g0, g1, o0, o1;
            upk2(acc[p][0], i0, i1);
            upk2(acc[p][1], g0, g1);
            upk2(acc[p][2], o0, o1);
            float bi = b3[jj], bg = b3[100 + jj], bo = b3[200 + jj];
            i0 += bi; i1 += bi; g0 += bg; g1 += bg; o0 += bo; o1 += bo;
            float c0 = fsig(i0) * ftanh_(g0);
            float c1 = fsig(i1) * ftanh_(g1);
            int bl = grp * 4 + 2 * p;
            h1bs[bl * 100 + jj]       = fsig(o0) * ftanh_(c0);
            h1bs[(bl + 1) * 100 + jj] = fsig(o1) * ftanh_(c1);
        }
    }
    __syncthreads();
    if (tid < 24) {
        int b = tid / 3, cls = tid - b * 3;
        float a = fcb[cls];
        const float* h1f = g_h1f + (size_t)(b0 + b) * 100;
        #pragma unroll 4
        for (int j = 0; j < 100; j++) {
            a += h1f[j]            * fcw[cls * 200 + j];
            a += h1bs[b * 100 + j] * fcw[cls * 200 + 100 + j];
        }
        lg[tid] = a;
    }
    __syncthreads();
    if (tid < 8) {
        int b = tid;
        float l0 = lg[b * 3], l1 = lg[b * 3 + 1], l2 = lg[b * 3 + 2];
        float m = fmaxf(l0, fmaxf(l1, l2));
        float e0 = __expf(l0 - m), e1 = __expf(l1 - m), e2 = __expf(l2 - m);
        float s = 1.0f / (e0 + e1 + e2);
        out[(b0 + b) * 3 + 0] = e0 * s;
        out[(b0 + b) * 3 + 1] = e1 * s;
        out[(b0 + b) * 3 + 2] = e2 * s;
    }
}

// ============================================================================
extern "C" void kernel_launch(void* const* d_in, const int* in_sizes, int n_in,
                              void* d_out, int out_size)
{
    (void)in_sizes; (void)n_in; (void)out_size;
    const float* x     = (const float*)d_in[0];
    const float* wih0f = (const float*)d_in[1];
    const float* whh0f = (const float*)d_in[2];
    const float* bih0f = (const float*)d_in[3];
    const float* bhh0f = (const float*)d_in[4];
    const float* wih0b = (const float*)d_in[5];
    const float* whh0b = (const float*)d_in[6];
    const float* bih0b = (const float*)d_in[7];
    const float* bhh0b = (const float*)d_in[8];
    const float* wih1f = (const float*)d_in[9];
    const float* whh1f = (const float*)d_in[10];
    const float* bih1f = (const float*)d_in[11];
    const float* bhh1f = (const float*)d_in[12];
    const float* wih1b = (const float*)d_in[13];
    const float* bih1b = (const float*)d_in[15];
    const float* bhh1b = (const float*)d_in[16];
    const float* fcw   = (const float*)d_in[17];
    const float* fcb   = (const float*)d_in[18];
    float* out = (float*)d_out;

    float* xg1p; cudaGetSymbolAddress((void**)&xg1p, g_xg1);

    cudaFuncSetAttribute(lstm_rec_mma,  cudaFuncAttributeMaxDynamicSharedMemorySize, RC_SMEM);
    cudaFuncSetAttribute(gemm_xg1_mma,  cudaFuncAttributeMaxDynamicSharedMemorySize, GSMEM);
    cudaFuncSetAttribute(lstm_final,    cudaFuncAttributeMaxDynamicSharedMemorySize, FN_SMEMF * 4);

    conv_b_kernel<<<(400 * 200 + 255) / 256, 256>>>(wih1f);
    lstm_rec_mma<<<128, NTHR, RC_SMEM>>>(nullptr, x, whh0f, whh0b, wih0f, wih0b,
                                         bih0f, bhh0f, bih0b, bhh0b, 0);
    gemm_xg1_mma<<<dim3(5, 1024), 256, GSMEM>>>(bih1f, bhh1f);
    lstm_rec_mma<<<64, NTHR, RC_SMEM>>>(xg1p, nullptr, whh1f, whh1f, wih1f, wih1f,
                                        bih1f, bhh1f, bih1f, bhh1f, 1);
    lstm_final<<<128, 256, FN_SMEMF * 4>>>(wih1b, bih1b, bhh1b, fcw, fcb, out);
}

// round 15
// speedup vs baseline: 3.0458x; 1.8234x over previous
#include <cuda_runtime.h>
#include <cuda_fp16.h>
#include <cstdint>

#define B 1024
#define T 128
#define INP 5
#define H 100
#define G4 400
#define MTOT (B*T)
#define KPAD 256          // k-stride of fp16 A/B arrays; 128B-aligned k-slices

// ---------------- scratch (device globals; no runtime allocation) ----------
__device__ float g_h0s[B * 2 * H];            // [b][200] h0 at t=T-1
// xg1 TILE layout: [(t*64+bg)*50 + tile][128]  (bg = batch-group of 16,
// tile = n'/8; inner order [g(8)][t4(4)][e(2)][hi(2)] -> one float4/lane)
__device__ float g_xg1[(size_t)MTOT * G4];
__device__ float g_h1f[B * H];
__device__ __half g_Ah[(size_t)MTOT * KPAD];  // h0 fp16, [t*B+b][k]; cols 200..255 = 0
__device__ __half g_Bh[400 * KPAD];           // W_ih_l1f fp16, rows gate-interleaved

typedef unsigned long long u64;

__device__ __forceinline__ u64 pk2(float a, float b) {
    u64 r; asm("mov.b64 %0, {%1,%2};" : "=l"(r) : "f"(a), "f"(b)); return r;
}
__device__ __forceinline__ void upk2(u64 v, float& a, float& b) {
    asm("mov.b64 {%0,%1}, %2;" : "=f"(a), "=f"(b) : "l"(v));
}
__device__ __forceinline__ u64 ffma2(u64 a, u64 b, u64 c) {
    asm("fma.rn.f32x2 %0, %1, %2, %0;" : "+l"(c) : "l"(a), "l"(b)); return c;
}
// ---- activations via tanh.approx (1 MUFU each; sigma = 0.5*tanh(x/2)+0.5) --
__device__ __forceinline__ float ftanh_(float x) {
    float t; asm("tanh.approx.f32 %0, %1;" : "=f"(t) : "f"(x)); return t;
}
__device__ __forceinline__ float fsig(float x) {
    float t; asm("tanh.approx.f32 %0, %1;" : "=f"(t) : "f"(x * 0.5f));
    return fmaf(0.5f, t, 0.5f);
}
__device__ __forceinline__ uint32_t smem_u32(const void* p) {
    uint32_t a;
    asm("{ .reg .u64 t; cvta.to.shared.u64 t, %1; cvt.u32.u64 %0, t; }" : "=r"(a) : "l"(p));
    return a;
}

#define MMA_F16(ac, a0,a1,a2,a3, b0,b1) \
    asm volatile("mma.sync.aligned.m16n8k16.row.col.f32.f16.f16.f32 " \
        "{%0,%1,%2,%3}, {%4,%5,%6,%7}, {%8,%9}, {%0,%1,%2,%3};" \
        : "+f"((ac)[0]), "+f"((ac)[1]), "+f"((ac)[2]), "+f"((ac)[3]) \
        : "r"(a0), "r"(a1), "r"(a2), "r"(a3), "r"(b0), "r"(b1))

#define CP_ASYNC16(dst, src) \
    asm volatile("cp.async.ca.shared.global [%0], [%1], 16;" :: "r"(dst), "l"(src))
#define CP_COMMIT() asm volatile("cp.async.commit_group;" ::: "memory")
#define CP_WAIT0()  asm volatile("cp.async.wait_group 0;" ::: "memory")

// ============================================================================
// TENSOR-CORE RECURRENCE, fp16 single-product (16 batches/CTA, 512 thr /
// 16 warps, 4 n-tile slots/warp, gate-interleaved n'=j*4+gate, ONE
// barrier/step; mode0 coalesced h copy to global; mode1 coalesced tile loads).
// SMEM: W[400][120]fp16 (96KB) | A bufs x2 (16x120 fp16 each)
// ============================================================================
#define KSB     240
#define OFF_A   96000
#define ABUF    3840
#define RC_SMEM (96000 + 2*3840)
#define NTHR    512

__global__ void __launch_bounds__(NTHR, 1) lstm_rec_mma(
    const float* __restrict__ xg,
    const float* __restrict__ x,
    const float* __restrict__ whf, const float* __restrict__ whb,
    const float* __restrict__ wihf, const float* __restrict__ wihb,
    const float* __restrict__ bihf, const float* __restrict__ bhhf,
    const float* __restrict__ bihb, const float* __restrict__ bhhb,
    int mode)
{
    extern __shared__ char smc[];
    const uint32_t sb = smem_u32(smc);
    const int tid = threadIdx.x, wid = tid >> 5, lane = tid & 31;
    const int g = lane >> 2, t4 = lane & 3;
    const int dir = (mode == 0) ? (int)(blockIdx.x >> 6) : 0;
    const int b0  = (mode == 0) ? (int)(blockIdx.x & 63) * 16 : (int)blockIdx.x * 16;
    const int bg  = b0 >> 4;
    const float* wp  = dir ? whb  : whf;
    const float* wip = dir ? wihb : wihf;
    const float* bi_ = dir ? bihb : bihf;
    const float* bh_ = dir ? bhhb : bhhf;

    for (int i = tid; i < (RC_SMEM >> 4); i += NTHR)
        ((uint4*)smc)[i] = make_uint4(0, 0, 0, 0);
    __syncthreads();
    // W fill: row n' = j*4+gate <- orig row gate*100+j ; k 0..99 = Whh
    for (int i = tid; i < 400 * 100; i += NTHR) {
        int r = i / 100, k = i - r * 100;
        int np = (r % 100) * 4 + r / 100;
        *(__half*)(smc + np * KSB + k * 2) = __float2half(wp[i]);
    }
    if (mode == 0) {
        for (int i = tid; i < 400 * INP; i += NTHR) {
            int r = i / INP, d = i - r * INP;
            int np = (r % 100) * 4 + r / 100;
            *(__half*)(smc + np * KSB + (100 + d) * 2) = __float2half(wip[i]);
        }
        if (tid < 16 * INP) {
            int bb = tid / INP, d = tid - (tid / INP) * INP;
            int tg0 = dir ? (T - 1) : 0;
            float xv = x[((size_t)(b0 + bb) * T + tg0) * INP + d];
            *(__half*)(smc + OFF_A + bb * KSB + (100 + d) * 2) = __float2half(xv);
        }
    }

    int  tl[4]; bool tv[4];
    float br[4][2];
    #pragma unroll
    for (int i = 0; i < 4; i++) {
        int t = wid + 16 * i;
        tv[i] = (t < 50); tl[i] = tv[i] ? t : 0;
        br[i][0] = br[i][1] = 0.f;
        if (mode == 0 && tv[i]) {
            int np = t * 8 + 2 * t4;
            int r0 = (np & 3) * 100 + (np >> 2);
            int r1 = ((np + 1) & 3) * 100 + ((np + 1) >> 2);
            br[i][0] = bi_[r0] + bh_[r0];
            br[i][1] = bi_[r1] + bh_[r1];
        }
    }
    float cst[4];
    #pragma unroll
    for (int i = 0; i < 4; i++) cst[i] = 0.f;

    // mode1: coalesced tile loads; lane reads float4 {c0, c2, c1, c3}
    float4 xp[4];
    if (mode == 1) {
        #pragma unroll
        for (int i = 0; i < 4; i++) {
            xp[i] = make_float4(0.f, 0.f, 0.f, 0.f);
            if (tv[i])
                xp[i] = *(const float4*)(xg + ((size_t)bg * 50 + tl[i]) * 128 + lane * 4);
        }
    }
    __syncthreads();

    for (int ts = 0; ts < T; ts++) {
        const int cur = ts & 1, nxt = cur ^ 1;
        const int tg = dir ? (T - 1 - ts) : ts;

        float acc[4][4];
        if (mode == 0) {
            #pragma unroll
            for (int i = 0; i < 4; i++) {
                acc[i][0] = br[i][0]; acc[i][1] = br[i][1];
                acc[i][2] = br[i][0]; acc[i][3] = br[i][1];
            }
        } else {
            #pragma unroll
            for (int i = 0; i < 4; i++) {
                acc[i][0] = xp[i].x; acc[i][1] = xp[i].z;   // c0, c1
                acc[i][2] = xp[i].y; acc[i][3] = xp[i].w;   // c2, c3
            }
            if (ts + 1 < T) {
                #pragma unroll
                for (int i = 0; i < 4; i++)
                    if (tv[i])
                        xp[i] = *(const float4*)(xg + (((size_t)(ts + 1) * 64 + bg) * 50 + tl[i]) * 128 + lane * 4);
            }
        }
        float xv = 0.f;
        if (mode == 0 && tid < 16 * INP && ts + 1 < T) {
            int bb = tid / INP, d = tid - (tid / INP) * INP;
            int tgn = dir ? (tg - 1) : (tg + 1);
            xv = x[((size_t)(b0 + bb) * T + tgn) * INP + d];
        }

        // ---- MMA: 7 k-chunks x 4 slots, single fp16 product ----
        const uint32_t aBase = sb + OFF_A + cur * ABUF;
        #pragma unroll
        for (int kc = 0; kc < 7; kc++) {
            uint32_t ah[4];
            uint32_t aa = aBase + (lane & 15) * KSB + (lane >> 4) * 16 + kc * 32;
            asm volatile("ldmatrix.sync.aligned.m8n8.x4.shared.b16 {%0,%1,%2,%3}, [%4];"
                : "=r"(ah[0]), "=r"(ah[1]), "=r"(ah[2]), "=r"(ah[3]) : "r"(aa));

            uint32_t wh[4][2];
            #pragma unroll
            for (int p = 0; p < 2; p++) {
                int m = lane >> 3;
                int tt = tl[2 * p + (m >> 1)];
                uint32_t wa = sb + (8 * tt + (lane & 7)) * KSB + (m & 1) * 16 + kc * 32;
                asm volatile("ldmatrix.sync.aligned.m8n8.x4.shared.b16 {%0,%1,%2,%3}, [%4];"
                    : "=r"(wh[2*p][0]), "=r"(wh[2*p][1]), "=r"(wh[2*p+1][0]), "=r"(wh[2*p+1][1])
                    : "r"(wa));
            }
            #pragma unroll
            for (int i = 0; i < 4; i++)
                MMA_F16(acc[i], ah[0], ah[1], ah[2], ah[3], wh[i][0], wh[i][1]);
        }

        // ---- gate exchange + in-register activations ----
        #pragma unroll
        for (int i = 0; i < 4; i++) {
            if (tv[i]) {
                float s0 = __shfl_xor_sync(0xffffffffu, acc[i][0], 1);
                float s1 = __shfl_xor_sync(0xffffffffu, acc[i][1], 1);
                float s2 = __shfl_xor_sync(0xffffffffu, acc[i][2], 1);
                float s3 = __shfl_xor_sync(0xffffffffu, acc[i][3], 1);
                bool odd = (t4 & 1);
                float gi = odd ? s2 : acc[i][0];
                float gf = odd ? s3 : acc[i][1];
                float gg = odd ? acc[i][2] : s0;
                float go = odd ? acc[i][3] : s1;
                float cv = fsig(gf) * cst[i] + fsig(gi) * ftanh_(gg);
                cst[i] = cv;
                float h = fsig(go) * ftanh_(cv);
                int bu = g + (odd ? 8 : 0);
                int ju = 2 * tl[i] + (t4 >> 1);
                *(__half*)(smc + OFF_A + nxt * ABUF + bu * KSB + ju * 2) = __float2half(h);
                if (mode == 0) {
                    if (tg == T - 1)
                        g_h0s[(size_t)(b0 + bu) * 200 + dir * 100 + ju] = h;
                } else if (ts == T - 1) {
                    g_h1f[(size_t)(b0 + bu) * 100 + ju] = h;
                }
            }
        }
        if (mode == 0 && tid < 16 * INP && ts + 1 < T) {
            int bb = tid / INP, d = tid - (tid / INP) * INP;
            *(__half*)(smc + OFF_A + nxt * ABUF + bb * KSB + (100 + d) * 2) = __float2half(xv);
        }
        __syncthreads();

        // ---- (mode0) coalesced copy of this step's h to global ----
        if (mode == 0) {
            const char* st = smc + OFF_A + nxt * ABUF;
            if (tid < 400) {
                int row = tid / 25, c8 = tid - row * 25;
                uint2 v = *(const uint2*)(st + row * KSB + c8 * 8);
                size_t gr = ((size_t)tg * B + b0 + row) * KPAD + dir * 100 + c8 * 4;
                *(uint2*)(g_Ah + gr) = v;
            }
        }
    }
}

// ============================================================================
// conv_b: W_ih_l1f -> fp16, rows gate-interleaved (n' = j*4+gate).
// ============================================================================
__global__ void conv_b_kernel(const float* __restrict__ wih)
{
    int i = blockIdx.x * 256 + threadIdx.x;
    if (i < 400 * 200) {
        int r = i / 200, k = i - r * 200;
        int np = (r % 100) * 4 + r / 100;
        g_Bh[np * KPAD + k] = __float2half(wih[i]);
    }
}

// ============================================================================
// xg1 GEMM fp16 single product: BM=128, BN=80, BK=64, 4 iters, cp.async
// double-buffered. Epilogue writes the TILE layout (dense float4/thread).
// grid (5, 1024).
// ============================================================================
#define GRS   72
#define GA_B  (128 * GRS * 2)
#define GB_B  (80 * GRS * 2)
#define GOFF_B  (2 * GA_B)
#define GOFF_BI (2 * GA_B + 2 * GB_B)
#define GSMEM   (GOFF_BI + 1600)

__global__ void __launch_bounds__(256, 3) gemm_xg1_mma(
    const float* __restrict__ bih, const float* __restrict__ bhh)
{
    extern __shared__ char gsm[];
    const uint32_t sbase = smem_u32(gsm);
    float* bsm = (float*)(gsm + GOFF_BI);

    const int tid  = threadIdx.x;
    const int wid  = tid >> 5;
    const int lane = tid & 31;
    const int n0   = blockIdx.x * 80;
    const int m0   = blockIdx.y * 128;
    const int wm   = (wid >> 1) * 32;
    const int wn   = (wid & 1) * 40;

    for (int i = tid; i < 400; i += 256) {
        int r = (i & 3) * 100 + (i >> 2);
        bsm[i] = bih[r] + bhh[r];
    }

    float acc[2][5][4];
    #pragma unroll
    for (int mt = 0; mt < 2; mt++)
        #pragma unroll
        for (int nt = 0; nt < 5; nt++)
            #pragma unroll
            for (int e = 0; e < 4; e++) acc[mt][nt][e] = 0.f;

    const int arow = tid >> 1, ahalf = tid & 1;
    const int brow = tid >> 1, bhalf = tid & 1;
    const uint32_t adst0 = sbase + arow * (GRS * 2) + ahalf * 64;
    const uint32_t bdst0 = sbase + GOFF_B + brow * (GRS * 2) + bhalf * 64;

    {
        const char* ap = (const char*)(g_Ah + (size_t)(m0 + arow) * KPAD + ahalf * 32);
        #pragma unroll
        for (int i = 0; i < 4; i++) CP_ASYNC16(adst0 + i * 16, ap + i * 16);
        if (tid < 160) {
            const char* bp = (const char*)(g_Bh + (size_t)(n0 + brow) * KPAD + bhalf * 32);
            #pragma unroll
            for (int i = 0; i < 4; i++) CP_ASYNC16(bdst0 + i * 16, bp + i * 16);
        }
        CP_COMMIT(); CP_WAIT0();
    }
    __syncthreads();

    for (int it = 0; it < 4; it++) {
        const int cur = it & 1, nxt = cur ^ 1;
        if (it < 3) {
            const int kc = it + 1;
            const char* ap = (const char*)(g_Ah + (size_t)(m0 + arow) * KPAD + kc * 64 + ahalf * 32);
            uint32_t ad = adst0 + nxt * GA_B;
            #pragma unroll
            for (int i = 0; i < 4; i++) CP_ASYNC16(ad + i * 16, ap + i * 16);
            if (tid < 160) {
                const char* bp = (const char*)(g_Bh + (size_t)(n0 + brow) * KPAD + kc * 64 + bhalf * 32);
                uint32_t bd = bdst0 + nxt * GB_B;
                #pragma unroll
                for (int i = 0; i < 4; i++) CP_ASYNC16(bd + i * 16, bp + i * 16);
            }
            CP_COMMIT();
        }

        const uint32_t abuf = sbase + cur * GA_B;
        const uint32_t bbuf = sbase + GOFF_B + cur * GB_B;
        #pragma unroll
        for (int kk = 0; kk < 4; kk++) {
            uint32_t af[2][4];
            #pragma unroll
            for (int mt = 0; mt < 2; mt++) {
                uint32_t addr = abuf + (wm + mt * 16 + (lane & 15)) * (GRS * 2)
                              + (lane >> 4) * 16 + kk * 32;
                asm volatile("ldmatrix.sync.aligned.m8n8.x4.shared.b16 {%0,%1,%2,%3}, [%4];"
                    : "=r"(af[mt][0]), "=r"(af[mt][1]), "=r"(af[mt][2]), "=r"(af[mt][3])
                    : "r"(addr));
            }
            uint32_t bf[5][2];
            #pragma unroll
            for (int nt = 0; nt < 5; nt++) {
                uint32_t addr = bbuf + (wn + nt * 8 + (lane & 7)) * (GRS * 2)
                              + ((lane >> 3) & 1) * 16 + kk * 32;
                asm volatile("ldmatrix.sync.aligned.m8n8.x2.shared.b16 {%0,%1}, [%2];"
                    : "=r"(bf[nt][0]), "=r"(bf[nt][1]) : "r"(addr));
            }
            #pragma unroll
            for (int mt = 0; mt < 2; mt++)
                #pragma unroll
                for (int nt = 0; nt < 5; nt++)
                    MMA_F16(acc[mt][nt], af[mt][0], af[mt][1], af[mt][2], af[mt][3],
                            bf[nt][0], bf[nt][1]);
        }

        if (it < 3) CP_WAIT0();
        __syncthreads();
    }

    // epilogue -> TILE layout: float4 {c0+b0, c2+b0, c1+b1, c3+b1} per (mt,nt)
    const int gid = lane >> 2, t4 = lane & 3;
    const int tq = m0 >> 10;
    #pragma unroll
    for (int mt = 0; mt < 2; mt++) {
        int bgq = (((m0 & 1023) + wm + mt * 16) >> 4);
        #pragma unroll
        for (int nt = 0; nt < 5; nt++) {
            int ncol = n0 + wn + nt * 8 + t4 * 2;
            int tile = (n0 + wn) / 8 + nt;
            float b0v = bsm[ncol], b1v = bsm[ncol + 1];
            float4 v = make_float4(acc[mt][nt][0] + b0v, acc[mt][nt][2] + b0v,
                                   acc[mt][nt][1] + b1v, acc[mt][nt][3] + b1v);
            *(float4*)(g_xg1 + (((size_t)tq * 64 + bgq) * 50 + tile) * 128
                       + (gid * 4 + t4) * 4) = v;
        }
    }
}

// ============================================================================
// lstm_final: layer1 backward single step (c0=0) + FC + softmax. grid 128.
// ============================================================================
#define FN_SMEMF (30000 + 200*10 + 800 + 300 + 600 + 4 + 24)

__global__ void __launch_bounds__(256, 1) lstm_final(
    const float* __restrict__ wih1b,
    const float* __restrict__ bih1b, const float* __restrict__ bhh1b,
    const float* __restrict__ fc_w,  const float* __restrict__ fc_b,
    float* __restrict__ out)
{
    extern __shared__ float sm[];
    float* wT   = sm;                    // [100 k][300]
    float* h0s  = sm + 30000;            // [200 k][10]
    float* h1bs = sm + 32000;            // [8][100]
    float* b3   = sm + 32800;            // [300]
    float* fcw  = sm + 33100;            // [600]
    float* fcb  = sm + 33700;            // [4]
    float* lg   = sm + 33704;            // [24]

    const int tid = threadIdx.x;
    const int b0 = blockIdx.x * 8;

    for (int i = tid; i < 8 * 200; i += 256) {
        int b = i / 200, k = i - b * 200;
        h0s[k * 10 + b] = g_h0s[(size_t)(b0 + b) * 200 + k];
    }
    for (int i = tid; i < 300; i += 256) {
        int g3 = i / 100, j = i - g3 * 100;
        int row = j + (g3 == 0 ? 0 : (g3 == 1 ? 200 : 300));
        b3[i] = bih1b[row] + bhh1b[row];
    }
    for (int i = tid; i < 600; i += 256) fcw[i] = fc_w[i];
    if (tid < 3) fcb[tid] = fc_b[tid];

    const int  jj  = tid & 127;
    const int  grp = tid >> 7;
    const bool act = (jj < H);

    u64 acc[2][3];
    #pragma unroll
    for (int p = 0; p < 2; p++)
        #pragma unroll
        for (int g = 0; g < 3; g++) acc[p][g] = pk2(0.f, 0.f);

    for (int kt = 0; kt < 2; kt++) {
        __syncthreads();
        for (int i = tid; i < 30000; i += 256) {
            int k = i % 100, j100 = i / 100;
            int grow = j100 + (j100 >= 100 ? 100 : 0);
            wT[k * 300 + j100] = wih1b[(size_t)grow * 200 + kt * 100 + k];
        }
        __syncthreads();
        if (act) {
            #pragma unroll 2
            for (int k = 0; k < 100; k++) {
                const float* wr = wT + k * 300 + jj;
                u64 w0 = pk2(wr[0], wr[0]);
                u64 w1 = pk2(wr[100], wr[100]);
                u64 w2 = pk2(wr[200], wr[200]);
                const float* hb = h0s + (kt * 100 + k) * 10 + grp * 4;
                #pragma unroll
                for (int p = 0; p < 2; p++) {
                    u64 hv = *(const u64*)(hb + 2 * p);
                    acc[p][0] = ffma2(w0, hv, acc[p][0]);
                    acc[p][1] = ffma2(w1, hv, acc[p][1]);
                    acc[p][2] = ffma2(w2, hv, acc[p][2]);
                }
            }
        }
    }
    if (act) {
        #pragma unroll
        for (int p = 0; p < 2; p++) {
            float i0, i1, g0, g1, o0, o1;
            upk2(acc[p][0], i0, i1);
            upk2(acc[p][1], g0, g1);
            upk2(acc[p][2], o0, o1);
            float bi = b3[jj], bg = b3[100 + jj], bo = b3[200 + jj];
            i0 += bi; i1 += bi; g0 += bg; g1 += bg; o0 += bo; o1 += bo;
            float c0 = fsig(i0) * ftanh_(g0);
            float c1 = fsig(i1) * ftanh_(g1);
            int bl = grp * 4 + 2 * p;
            h1bs[bl * 100 + jj]       = fsig(o0) * ftanh_(c0);
            h1bs[(bl + 1) * 100 + jj] = fsig(o1) * ftanh_(c1);
        }
    }
    __syncthreads();
    if (tid < 24) {
        int b = tid / 3, cls = tid - b * 3;
        float a = fcb[cls];
        const float* h1f = g_h1f + (size_t)(b0 + b) * 100;
        #pragma unroll 4
        for (int j = 0; j < 100; j++) {
            a += h1f[j]            * fcw[cls * 200 + j];
            a += h1bs[b * 100 + j] * fcw[cls * 200 + 100 + j];
        }
        lg[tid] = a;
    }
    __syncthreads();
    if (tid < 8) {
        int b = tid;
        float l0 = lg[b * 3], l1 = lg[b * 3 + 1], l2 = lg[b * 3 + 2];
        float m = fmaxf(l0, fmaxf(l1, l2));
        float e0 = __expf(l0 - m), e1 = __expf(l1 - m), e2 = __expf(l2 - m);
        float s = 1.0f / (e0 + e1 + e2);
        out[(b0 + b) * 3 + 0] = e0 * s;
        out[(b0 + b) * 3 + 1] = e1 * s;
        out[(b0 + b) * 3 + 2] = e2 * s;
    }
}

// ============================================================================
extern "C" void kernel_launch(void* const* d_in, const int* in_sizes, int n_in,
                              void* d_out, int out_size)
{
    (void)in_sizes; (void)n_in; (void)out_size;
    const float* x     = (const float*)d_in[0];
    const float* wih0f = (const float*)d_in[1];
    const float* whh0f = (const float*)d_in[2];
    const float* bih0f = (const float*)d_in[3];
    const float* bhh0f = (const float*)d_in[4];
    const float* wih0b = (const float*)d_in[5];
    const float* whh0b = (const float*)d_in[6];
    const float* bih0b = (const float*)d_in[7];
    const float* bhh0b = (const float*)d_in[8];
    const float* wih1f = (const float*)d_in[9];
    const float* whh1f = (const float*)d_in[10];
    const float* bih1f = (const float*)d_in[11];
    const float* bhh1f = (const float*)d_in[12];
    const float* wih1b = (const float*)d_in[13];
    const float* bih1b = (const float*)d_in[15];
    const float* bhh1b = (const float*)d_in[16];
    const float* fcw   = (const float*)d_in[17];
    const float* fcb   = (const float*)d_in[18];
    float* out = (float*)d_out;

    float* xg1p; cudaGetSymbolAddress((void**)&xg1p, g_xg1);

    cudaFuncSetAttribute(lstm_rec_mma,  cudaFuncAttributeMaxDynamicSharedMemorySize, RC_SMEM);
    cudaFuncSetAttribute(gemm_xg1_mma,  cudaFuncAttributeMaxDynamicSharedMemorySize, GSMEM);
    cudaFuncSetAttribute(lstm_final,    cudaFuncAttributeMaxDynamicSharedMemorySize, FN_SMEMF * 4);

    conv_b_kernel<<<(400 * 200 + 255) / 256, 256>>>(wih1f);
    lstm_rec_mma<<<128, NTHR, RC_SMEM>>>(nullptr, x, whh0f, whh0b, wih0f, wih0b,
                                         bih0f, bhh0f, bih0b, bhh0b, 0);
    gemm_xg1_mma<<<dim3(5, 1024), 256, GSMEM>>>(bih1f, bhh1f);
    lstm_rec_mma<<<64, NTHR, RC_SMEM>>>(xg1p, nullptr, whh1f, whh1f, wih1f, wih1f,
                                        bih1f, bhh1f, bih1f, bhh1f, 1);
    lstm_final<<<128, 256, FN_SMEMF * 4>>>(wih1b, bih1b, bhh1b, fcw, fcb, out);
}

// round 16
// speedup vs baseline: 3.4395x; 1.1292x over previous
#include <cuda_runtime.h>
#include <cuda_fp16.h>
#include <cstdint>

#define B 1024
#define T 128
#define INP 5
#define H 100
#define G4 400
#define MTOT (B*T)
#define KPAD 256          // k-stride of fp16 A/B arrays; 128B-aligned k-slices

// ---------------- scratch (device globals; no runtime allocation) ----------
__device__ float g_h0s[B * 2 * H];            // [b][200] h0 at t=T-1
// xg1 TILE layout: [(t*64+bg)*50 + tile][128]
__device__ float g_xg1[(size_t)MTOT * G4];
__device__ float g_h1f[B * H];
__device__ __half g_Ah[(size_t)MTOT * KPAD];  // h0 fp16, [t*B+b][k]; cols 200..255 = 0
__device__ __half g_Bh[400 * KPAD];           // W_ih_l1f fp16, rows gate-interleaved

typedef unsigned long long u64;

__device__ __forceinline__ u64 pk2(float a, float b) {
    u64 r; asm("mov.b64 %0, {%1,%2};" : "=l"(r) : "f"(a), "f"(b)); return r;
}
__device__ __forceinline__ void upk2(u64 v, float& a, float& b) {
    asm("mov.b64 {%0,%1}, %2;" : "=f"(a), "=f"(b) : "l"(v));
}
__device__ __forceinline__ u64 ffma2(u64 a, u64 b, u64 c) {
    asm("fma.rn.f32x2 %0, %1, %2, %0;" : "+l"(c) : "l"(a), "l"(b)); return c;
}
// ---- activations via tanh.approx (1 MUFU each; sigma = 0.5*tanh(x/2)+0.5) --
__device__ __forceinline__ float ftanh_(float x) {
    float t; asm("tanh.approx.f32 %0, %1;" : "=f"(t) : "f"(x)); return t;
}
__device__ __forceinline__ float fsig(float x) {
    float t; asm("tanh.approx.f32 %0, %1;" : "=f"(t) : "f"(x * 0.5f));
    return fmaf(0.5f, t, 0.5f);
}
__device__ __forceinline__ uint32_t smem_u32(const void* p) {
    uint32_t a;
    asm("{ .reg .u64 t; cvta.to.shared.u64 t, %1; cvt.u32.u64 %0, t; }" : "=r"(a) : "l"(p));
    return a;
}

#define MMA_F16(ac, a0,a1,a2,a3, b0,b1) \
    asm volatile("mma.sync.aligned.m16n8k16.row.col.f32.f16.f16.f32 " \
        "{%0,%1,%2,%3}, {%4,%5,%6,%7}, {%8,%9}, {%0,%1,%2,%3};" \
        : "+f"((ac)[0]), "+f"((ac)[1]), "+f"((ac)[2]), "+f"((ac)[3]) \
        : "r"(a0), "r"(a1), "r"(a2), "r"(a3), "r"(b0), "r"(b1))

#define CP_ASYNC16(dst, src) \
    asm volatile("cp.async.ca.shared.global [%0], [%1], 16;" :: "r"(dst), "l"(src))
#define CP_COMMIT() asm volatile("cp.async.commit_group;" ::: "memory")
#define CP_WAIT0()  asm volatile("cp.async.wait_group 0;" ::: "memory")

// ============================================================================
// TENSOR-CORE RECURRENCE, fp16 single-product, W FRAGMENTS HOISTED TO
// REGISTERS (56 regs; loaded once, reused 128 steps -> per-step LDSM 28->7).
// 16 batches/CTA, 512 thr / 16 warps, 4 n-tile slots/warp, gate-interleaved
// n'=j*4+gate, ONE barrier/step; mode0 coalesced h copy to global; mode1
// coalesced tile loads of xg.
// SMEM: W[400][120]fp16 (96KB, used only during fragment preload) | A bufs x2
// ============================================================================
#define KSB     240
#define OFF_A   96000
#define ABUF    3840
#define RC_SMEM (96000 + 2*3840)
#define NTHR    512

__global__ void __launch_bounds__(NTHR, 1) lstm_rec_mma(
    const float* __restrict__ xg,
    const float* __restrict__ x,
    const float* __restrict__ whf, const float* __restrict__ whb,
    const float* __restrict__ wihf, const float* __restrict__ wihb,
    const float* __restrict__ bihf, const float* __restrict__ bhhf,
    const float* __restrict__ bihb, const float* __restrict__ bhhb,
    int mode)
{
    extern __shared__ char smc[];
    const uint32_t sb = smem_u32(smc);
    const int tid = threadIdx.x, wid = tid >> 5, lane = tid & 31;
    const int g = lane >> 2, t4 = lane & 3;
    const int dir = (mode == 0) ? (int)(blockIdx.x >> 6) : 0;
    const int b0  = (mode == 0) ? (int)(blockIdx.x & 63) * 16 : (int)blockIdx.x * 16;
    const int bg  = b0 >> 4;
    const float* wp  = dir ? whb  : whf;
    const float* wip = dir ? wihb : wihf;
    const float* bi_ = dir ? bihb : bihf;
    const float* bh_ = dir ? bhhb : bhhf;

    for (int i = tid; i < (RC_SMEM >> 4); i += NTHR)
        ((uint4*)smc)[i] = make_uint4(0, 0, 0, 0);
    __syncthreads();
    // W fill: row n' = j*4+gate <- orig row gate*100+j ; k 0..99 = Whh
    for (int i = tid; i < 400 * 100; i += NTHR) {
        int r = i / 100, k = i - r * 100;
        int np = (r % 100) * 4 + r / 100;
        *(__half*)(smc + np * KSB + k * 2) = __float2half(wp[i]);
    }
    if (mode == 0) {
        for (int i = tid; i < 400 * INP; i += NTHR) {
            int r = i / INP, d = i - r * INP;
            int np = (r % 100) * 4 + r / 100;
            *(__half*)(smc + np * KSB + (100 + d) * 2) = __float2half(wip[i]);
        }
        if (tid < 16 * INP) {
            int bb = tid / INP, d = tid - (tid / INP) * INP;
            int tg0 = dir ? (T - 1) : 0;
            float xv = x[((size_t)(b0 + bb) * T + tg0) * INP + d];
            *(__half*)(smc + OFF_A + bb * KSB + (100 + d) * 2) = __float2half(xv);
        }
    }

    int  tl[4]; bool tv[4];
    float br[4][2];
    #pragma unroll
    for (int i = 0; i < 4; i++) {
        int t = wid + 16 * i;
        tv[i] = (t < 50); tl[i] = tv[i] ? t : 0;
        br[i][0] = br[i][1] = 0.f;
        if (mode == 0 && tv[i]) {
            int np = t * 8 + 2 * t4;
            int r0 = (np & 3) * 100 + (np >> 2);
            int r1 = ((np + 1) & 3) * 100 + ((np + 1) >> 2);
            br[i][0] = bi_[r0] + bh_[r0];
            br[i][1] = bi_[r1] + bh_[r1];
        }
    }
    float cst[4];
    #pragma unroll
    for (int i = 0; i < 4; i++) cst[i] = 0.f;

    __syncthreads();   // W smem complete before fragment preload

    // ---- HOIST: load all W fragments into registers ONCE ----
    uint32_t wreg[7][4][2];
    #pragma unroll
    for (int kc = 0; kc < 7; kc++) {
        #pragma unroll
        for (int p = 0; p < 2; p++) {
            int m = lane >> 3;
            int tt = tl[2 * p + (m >> 1)];
            uint32_t wa = sb + (8 * tt + (lane & 7)) * KSB + (m & 1) * 16 + kc * 32;
            asm volatile("ldmatrix.sync.aligned.m8n8.x4.shared.b16 {%0,%1,%2,%3}, [%4];"
                : "=r"(wreg[kc][2*p][0]), "=r"(wreg[kc][2*p][1]),
                  "=r"(wreg[kc][2*p+1][0]), "=r"(wreg[kc][2*p+1][1])
                : "r"(wa));
        }
    }

    // mode1: coalesced tile loads; lane reads float4 {c0, c2, c1, c3}
    float4 xp[4];
    if (mode == 1) {
        #pragma unroll
        for (int i = 0; i < 4; i++) {
            xp[i] = make_float4(0.f, 0.f, 0.f, 0.f);
            if (tv[i])
                xp[i] = *(const float4*)(xg + ((size_t)bg * 50 + tl[i]) * 128 + lane * 4);
        }
    }

    for (int ts = 0; ts < T; ts++) {
        const int cur = ts & 1, nxt = cur ^ 1;
        const int tg = dir ? (T - 1 - ts) : ts;

        float acc[4][4];
        if (mode == 0) {
            #pragma unroll
            for (int i = 0; i < 4; i++) {
                acc[i][0] = br[i][0]; acc[i][1] = br[i][1];
                acc[i][2] = br[i][0]; acc[i][3] = br[i][1];
            }
        } else {
            #pragma unroll
            for (int i = 0; i < 4; i++) {
                acc[i][0] = xp[i].x; acc[i][1] = xp[i].z;   // c0, c1
                acc[i][2] = xp[i].y; acc[i][3] = xp[i].w;   // c2, c3
            }
            if (ts + 1 < T) {
                #pragma unroll
                for (int i = 0; i < 4; i++)
                    if (tv[i])
                        xp[i] = *(const float4*)(xg + (((size_t)(ts + 1) * 64 + bg) * 50 + tl[i]) * 128 + lane * 4);
            }
        }
        float xv = 0.f;
        if (mode == 0 && tid < 16 * INP && ts + 1 < T) {
            int bb = tid / INP, d = tid - (tid / INP) * INP;
            int tgn = dir ? (tg - 1) : (tg + 1);
            xv = x[((size_t)(b0 + bb) * T + tgn) * INP + d];
        }

        // ---- MMA: 7 k-chunks x 4 slots; W from registers, A via ldmatrix ----
        const uint32_t aBase = sb + OFF_A + cur * ABUF;
        #pragma unroll
        for (int kc = 0; kc < 7; kc++) {
            uint32_t ah[4];
            uint32_t aa = aBase + (lane & 15) * KSB + (lane >> 4) * 16 + kc * 32;
            asm volatile("ldmatrix.sync.aligned.m8n8.x4.shared.b16 {%0,%1,%2,%3}, [%4];"
                : "=r"(ah[0]), "=r"(ah[1]), "=r"(ah[2]), "=r"(ah[3]) : "r"(aa));
            #pragma unroll
            for (int i = 0; i < 4; i++)
                MMA_F16(acc[i], ah[0], ah[1], ah[2], ah[3],
                        wreg[kc][i][0], wreg[kc][i][1]);
        }

        // ---- gate exchange + in-register activations ----
        #pragma unroll
        for (int i = 0; i < 4; i++) {
            if (tv[i]) {
                float s0 = __shfl_xor_sync(0xffffffffu, acc[i][0], 1);
                float s1 = __shfl_xor_sync(0xffffffffu, acc[i][1], 1);
                float s2 = __shfl_xor_sync(0xffffffffu, acc[i][2], 1);
                float s3 = __shfl_xor_sync(0xffffffffu, acc[i][3], 1);
                bool odd = (t4 & 1);
                float gi = odd ? s2 : acc[i][0];
                float gf = odd ? s3 : acc[i][1];
                float gg = odd ? acc[i][2] : s0;
                float go = odd ? acc[i][3] : s1;
                float cv = fsig(gf) * cst[i] + fsig(gi) * ftanh_(gg);
                cst[i] = cv;
                float h = fsig(go) * ftanh_(cv);
                int bu = g + (odd ? 8 : 0);
                int ju = 2 * tl[i] + (t4 >> 1);
                *(__half*)(smc + OFF_A + nxt * ABUF + bu * KSB + ju * 2) = __float2half(h);
                if (mode == 0) {
                    if (tg == T - 1)
                        g_h0s[(size_t)(b0 + bu) * 200 + dir * 100 + ju] = h;
                } else if (ts == T - 1) {
                    g_h1f[(size_t)(b0 + bu) * 100 + ju] = h;
                }
            }
        }
        if (mode == 0 && tid < 16 * INP && ts + 1 < T) {
            int bb = tid / INP, d = tid - (tid / INP) * INP;
            *(__half*)(smc + OFF_A + nxt * ABUF + bb * KSB + (100 + d) * 2) = __float2half(xv);
        }
        __syncthreads();

        // ---- (mode0) coalesced copy of this step's h to global ----
        if (mode == 0) {
            const char* st = smc + OFF_A + nxt * ABUF;
            if (tid < 400) {
                int row = tid / 25, c8 = tid - row * 25;
                uint2 v = *(const uint2*)(st + row * KSB + c8 * 8);
                size_t gr = ((size_t)tg * B + b0 + row) * KPAD + dir * 100 + c8 * 4;
                *(uint2*)(g_Ah + gr) = v;
            }
        }
    }
}

// ============================================================================
// conv_b: W_ih_l1f -> fp16, rows gate-interleaved (n' = j*4+gate).
// ============================================================================
__global__ void conv_b_kernel(const float* __restrict__ wih)
{
    int i = blockIdx.x * 256 + threadIdx.x;
    if (i < 400 * 200) {
        int r = i / 200, k = i - r * 200;
        int np = (r % 100) * 4 + r / 100;
        g_Bh[np * KPAD + k] = __float2half(wih[i]);
    }
}

// ============================================================================
// xg1 GEMM fp16 single product: BM=128, BN=80, BK=64, 4 iters, cp.async
// double-buffered; TILE-layout epilogue. grid (5, 1024).
// ============================================================================
#define GRS   72
#define GA_B  (128 * GRS * 2)
#define GB_B  (80 * GRS * 2)
#define GOFF_B  (2 * GA_B)
#define GOFF_BI (2 * GA_B + 2 * GB_B)
#define GSMEM   (GOFF_BI + 1600)

__global__ void __launch_bounds__(256, 3) gemm_xg1_mma(
    const float* __restrict__ bih, const float* __restrict__ bhh)
{
    extern __shared__ char gsm[];
    const uint32_t sbase = smem_u32(gsm);
    float* bsm = (float*)(gsm + GOFF_BI);

    const int tid  = threadIdx.x;
    const int wid  = tid >> 5;
    const int lane = tid & 31;
    const int n0   = blockIdx.x * 80;
    const int m0   = blockIdx.y * 128;
    const int wm   = (wid >> 1) * 32;
    const int wn   = (wid & 1) * 40;

    for (int i = tid; i < 400; i += 256) {
        int r = (i & 3) * 100 + (i >> 2);
        bsm[i] = bih[r] + bhh[r];
    }

    float acc[2][5][4];
    #pragma unroll
    for (int mt = 0; mt < 2; mt++)
        #pragma unroll
        for (int nt = 0; nt < 5; nt++)
            #pragma unroll
            for (int e = 0; e < 4; e++) acc[mt][nt][e] = 0.f;

    const int arow = tid >> 1, ahalf = tid & 1;
    const int brow = tid >> 1, bhalf = tid & 1;
    const uint32_t adst0 = sbase + arow * (GRS * 2) + ahalf * 64;
    const uint32_t bdst0 = sbase + GOFF_B + brow * (GRS * 2) + bhalf * 64;

    {
        const char* ap = (const char*)(g_Ah + (size_t)(m0 + arow) * KPAD + ahalf * 32);
        #pragma unroll
        for (int i = 0; i < 4; i++) CP_ASYNC16(adst0 + i * 16, ap + i * 16);
        if (tid < 160) {
            const char* bp = (const char*)(g_Bh + (size_t)(n0 + brow) * KPAD + bhalf * 32);
            #pragma unroll
            for (int i = 0; i < 4; i++) CP_ASYNC16(bdst0 + i * 16, bp + i * 16);
        }
        CP_COMMIT(); CP_WAIT0();
    }
    __syncthreads();

    for (int it = 0; it < 4; it++) {
        const int cur = it & 1, nxt = cur ^ 1;
        if (it < 3) {
            const int kc = it + 1;
            const char* ap = (const char*)(g_Ah + (size_t)(m0 + arow) * KPAD + kc * 64 + ahalf * 32);
            uint32_t ad = adst0 + nxt * GA_B;
            #pragma unroll
            for (int i = 0; i < 4; i++) CP_ASYNC16(ad + i * 16, ap + i * 16);
            if (tid < 160) {
                const char* bp = (const char*)(g_Bh + (size_t)(n0 + brow) * KPAD + kc * 64 + bhalf * 32);
                uint32_t bd = bdst0 + nxt * GB_B;
                #pragma unroll
                for (int i = 0; i < 4; i++) CP_ASYNC16(bd + i * 16, bp + i * 16);
            }
            CP_COMMIT();
        }

        const uint32_t abuf = sbase + cur * GA_B;
        const uint32_t bbuf = sbase + GOFF_B + cur * GB_B;
        #pragma unroll
        for (int kk = 0; kk < 4; kk++) {
            uint32_t af[2][4];
            #pragma unroll
            for (int mt = 0; mt < 2; mt++) {
                uint32_t addr = abuf + (wm + mt * 16 + (lane & 15)) * (GRS * 2)
                              + (lane >> 4) * 16 + kk * 32;
                asm volatile("ldmatrix.sync.aligned.m8n8.x4.shared.b16 {%0,%1,%2,%3}, [%4];"
                    : "=r"(af[mt][0]), "=r"(af[mt][1]), "=r"(af[mt][2]), "=r"(af[mt][3])
                    : "r"(addr));
            }
            uint32_t bf[5][2];
            #pragma unroll
            for (int nt = 0; nt < 5; nt++) {
                uint32_t addr = bbuf + (wn + nt * 8 + (lane & 7)) * (GRS * 2)
                              + ((lane >> 3) & 1) * 16 + kk * 32;
                asm volatile("ldmatrix.sync.aligned.m8n8.x2.shared.b16 {%0,%1}, [%2];"
                    : "=r"(bf[nt][0]), "=r"(bf[nt][1]) : "r"(addr));
            }
            #pragma unroll
            for (int mt = 0; mt < 2; mt++)
                #pragma unroll
                for (int nt = 0; nt < 5; nt++)
                    MMA_F16(acc[mt][nt], af[mt][0], af[mt][1], af[mt][2], af[mt][3],
                            bf[nt][0], bf[nt][1]);
        }

        if (it < 3) CP_WAIT0();
        __syncthreads();
    }

    const int gid = lane >> 2, t4 = lane & 3;
    const int tq = m0 >> 10;
    #pragma unroll
    for (int mt = 0; mt < 2; mt++) {
        int bgq = (((m0 & 1023) + wm + mt * 16) >> 4);
        #pragma unroll
        for (int nt = 0; nt < 5; nt++) {
            int ncol = n0 + wn + nt * 8 + t4 * 2;
            int tile = (n0 + wn) / 8 + nt;
            float b0v = bsm[ncol], b1v = bsm[ncol + 1];
            float4 v = make_float4(acc[mt][nt][0] + b0v, acc[mt][nt][2] + b0v,
                                   acc[mt][nt][1] + b1v, acc[mt][nt][3] + b1v);
            *(float4*)(g_xg1 + (((size_t)tq * 64 + bgq) * 50 + tile) * 128
                       + (gid * 4 + t4) * 4) = v;
        }
    }
}

// ============================================================================
// lstm_final: layer1 backward single step (c0=0) + FC + softmax. grid 128.
// ============================================================================
#define FN_SMEMF (30000 + 200*10 + 800 + 300 + 600 + 4 + 24)

__global__ void __launch_bounds__(256, 1) lstm_final(
    const float* __restrict__ wih1b,
    const float* __restrict__ bih1b, const float* __restrict__ bhh1b,
    const float* __restrict__ fc_w,  const float* __restrict__ fc_b,
    float* __restrict__ out)
{
    extern __shared__ float sm[];
    float* wT   = sm;
    float* h0s  = sm + 30000;
    float* h1bs = sm + 32000;
    float* b3   = sm + 32800;
    float* fcw  = sm + 33100;
    float* fcb  = sm + 33700;
    float* lg   = sm + 33704;

    const int tid = threadIdx.x;
    const int b0 = blockIdx.x * 8;

    for (int i = tid; i < 8 * 200; i += 256) {
        int b = i / 200, k = i - b * 200;
        h0s[k * 10 + b] = g_h0s[(size_t)(b0 + b) * 200 + k];
    }
    for (int i = tid; i < 300; i += 256) {
        int g3 = i / 100, j = i - g3 * 100;
        int row = j + (g3 == 0 ? 0 : (g3 == 1 ? 200 : 300));
        b3[i] = bih1b[row] + bhh1b[row];
    }
    for (int i = tid; i < 600; i += 256) fcw[i] = fc_w[i];
    if (tid < 3) fcb[tid] = fc_b[tid];

    const int  jj  = tid & 127;
    const int  grp = tid >> 7;
    const bool act = (jj < H);

    u64 acc[2][3];
    #pragma unroll
    for (int p = 0; p < 2; p++)
        #pragma unroll
        for (int g = 0; g < 3; g++) acc[p][g] = pk2(0.f, 0.f);

    for (int kt = 0; kt < 2; kt++) {
        __syncthreads();
        for (int i = tid; i < 30000; i += 256) {
            int k = i % 100, j100 = i / 100;
            int grow = j100 + (j100 >= 100 ? 100 : 0);
            wT[k * 300 + j100] = wih1b[(size_t)grow * 200 + kt * 100 + k];
        }
        __syncthreads();
        if (act) {
            #pragma unroll 2
            for (int k = 0; k < 100; k++) {
                const float* wr = wT + k * 300 + jj;
                u64 w0 = pk2(wr[0], wr[0]);
                u64 w1 = pk2(wr[100], wr[100]);
                u64 w2 = pk2(wr[200], wr[200]);
                const float* hb = h0s + (kt * 100 + k) * 10 + grp * 4;
                #pragma unroll
                for (int p = 0; p < 2; p++) {
                    u64 hv = *(const u64*)(hb + 2 * p);
                    acc[p][0] = ffma2(w0, hv, acc[p][0]);
                    acc[p][1] = ffma2(w1, hv, acc[p][1]);
                    acc[p][2] = ffma2(w2, hv, acc[p][2]);
                }
            }
        }
    }
    if (act) {
        #pragma unroll
        for (int p = 0; p < 2; p++) {
            float i0, i1, g0, g1, o0, o1;
            upk2(acc[p][0], i0, i1);
            upk2(acc[p][1], g0, g1);
            upk2(acc[p][2], o0, o1);
            float bi = b3[jj], bg = b3[100 + jj], bo = b3[200 + jj];
            i0 += bi; i1 += bi; g0 += bg; g1 += bg; o0 += bo; o1 += bo;
            float c0 = fsig(i0) * ftanh_(g0);
            float c1 = fsig(i1) * ftanh_(g1);
            int bl = grp * 4 + 2 * p;
            h1bs[bl * 100 + jj]       = fsig(o0) * ftanh_(c0);
            h1bs[(bl + 1) * 100 + jj] = fsig(o1) * ftanh_(c1);
        }
    }
    __syncthreads();
    if (tid < 24) {
        int b = tid / 3, cls = tid - b * 3;
        float a = fcb[cls];
        const float* h1f = g_h1f + (size_t)(b0 + b) * 100;
        #pragma unroll 4
        for (int j = 0; j < 100; j++) {
            a += h1f[j]            * fcw[cls * 200 + j];
            a += h1bs[b * 100 + j] * fcw[cls * 200 + 100 + j];
        }
        lg[tid] = a;
    }
    __syncthreads();
    if (tid < 8) {
        int b = tid;
        float l0 = lg[b * 3], l1 = lg[b * 3 + 1], l2 = lg[b * 3 + 2];
        float m = fmaxf(l0, fmaxf(l1, l2));
        float e0 = __expf(l0 - m), e1 = __expf(l1 - m), e2 = __expf(l2 - m);
        float s = 1.0f / (e0 + e1 + e2);
        out[(b0 + b) * 3 + 0] = e0 * s;
        out[(b0 + b) * 3 + 1] = e1 * s;
        out[(b0 + b) * 3 + 2] = e2 * s;
    }
}

// ============================================================================
extern "C" void kernel_launch(void* const* d_in, const int* in_sizes, int n_in,
                              void* d_out, int out_size)
{
    (void)in_sizes; (void)n_in; (void)out_size;
    const float* x     = (const float*)d_in[0];
    const float* wih0f = (const float*)d_in[1];
    const float* whh0f = (const float*)d_in[2];
    const float* bih0f = (const float*)d_in[3];
    const float* bhh0f = (const float*)d_in[4];
    const float* wih0b = (const float*)d_in[5];
    const float* whh0b = (const float*)d_in[6];
    const float* bih0b = (const float*)d_in[7];
    const float* bhh0b = (const float*)d_in[8];
    const float* wih1f = (const float*)d_in[9];
    const float* whh1f = (const float*)d_in[10];
    const float* bih1f = (const float*)d_in[11];
    const float* bhh1f = (const float*)d_in[12];
    const float* wih1b = (const float*)d_in[13];
    const float* bih1b = (const float*)d_in[15];
    const float* bhh1b = (const float*)d_in[16];
    const float* fcw   = (const float*)d_in[17];
    const float* fcb   = (const float*)d_in[18];
    float* out = (float*)d_out;

    float* xg1p; cudaGetSymbolAddress((void**)&xg1p, g_xg1);

    cudaFuncSetAttribute(lstm_rec_mma,  cudaFuncAttributeMaxDynamicSharedMemorySize, RC_SMEM);
    cudaFuncSetAttribute(gemm_xg1_mma,  cudaFuncAttributeMaxDynamicSharedMemorySize, GSMEM);
    cudaFuncSetAttribute(lstm_final,    cudaFuncAttributeMaxDynamicSharedMemorySize, FN_SMEMF * 4);

    conv_b_kernel<<<(400 * 200 + 255) / 256, 256>>>(wih1f);
    lstm_rec_mma<<<128, NTHR, RC_SMEM>>>(nullptr, x, whh0f, whh0b, wih0f, wih0b,
                                         bih0f, bhh0f, bih0b, bhh0b, 0);
    gemm_xg1_mma<<<dim3(5, 1024), 256, GSMEM>>>(bih1f, bhh1f);
    lstm_rec_mma<<<64, NTHR, RC_SMEM>>>(xg1p, nullptr, whh1f, whh1f, wih1f, wih1f,
                                        bih1f, bhh1f, bih1f, bhh1f, 1);
    lstm_final<<<128, 256, FN_SMEMF * 4>>>(wih1b, bih1b, bhh1b, fcw, fcb, out);
}